// round 8
// baseline (speedup 1.0000x reference)
#include <cuda_runtime.h>
#include <cmath>

// Problem constants
#define LSTEPS 47
#define RR 24
#define OO 24
#define BB 64
#define EMB 128
#define HH 256
#define M1 1536        // RR * BB
#define MALL 72192     // LSTEPS * M1
#define NBLK 144       // persistent grid (12 x 12)

#define OUT_ALL_ELEMS 36962304   // M1 * LSTEPS * 512
#define HID_ELEMS 393216         // BB * 24 * HH

// Scratch
__device__ float d_xy[(size_t)MALL * 256];    // [x | y] packed tf32
__device__ float d_qkv[(size_t)MALL * 384];
__device__ float d_att[(size_t)MALL * 128];   // tf32-rounded
__device__ float d_pre[(size_t)MALL * 1536];
__device__ float d_ht[2 * M1 * 512];          // tf32 state ping-pong [h_row|h_col]
__device__ float d_g[M1 * 1536];
__device__ float d_Wt[1536 * 768];            // tf32-rounded W
__device__ float d_inwt[384 * 128];
__device__ float d_outwt[128 * 128];
__device__ unsigned d_barcnt;                 // persistent-kernel grid barrier

__device__ __forceinline__ unsigned f2tf(float x) {
    unsigned u; asm("cvt.rna.tf32.f32 %0, %1;" : "=r"(u) : "f"(x)); return u;
}
__device__ __forceinline__ float f2tff(float x) { return __uint_as_float(f2tf(x)); }
__device__ __forceinline__ float4 tf4(float4 v) {
    return make_float4(f2tff(v.x), f2tff(v.y), f2tff(v.z), f2tff(v.w));
}

// ---------------------------------------------------------------------------
__global__ void cvt_kernel(const float* __restrict__ src, float* __restrict__ dst, int n4) {
    int i = blockIdx.x * 256 + threadIdx.x;
    if (i >= n4) return;
    ((float4*)dst)[i] = tf4(((const float4*)src)[i]);
}

// ---------------------------------------------------------------------------
// build x (tf32): xy[m*256 + i] = input[b, l-r, r, i] (zero outside)
// ---------------------------------------------------------------------------
__global__ void build_x_kernel(const float* __restrict__ input, float* __restrict__ xy) {
    int idx = blockIdx.x * 256 + threadIdx.x;
    if (idx >= MALL * 32) return;
    int c = idx & 31;
    int m = idx >> 5;
    int b = m & 63;
    int t = m >> 6;
    int r = t % RR;
    int l = t / RR;
    int o = l - r;
    float4 v = make_float4(0.f, 0.f, 0.f, 0.f);
    if (o >= 0 && o < OO)
        v = tf4(((const float4*)(input + (size_t)((b * OO + o) * RR + r) * EMB))[c]);
    ((float4*)(xy + (size_t)m * 256))[c] = v;
}

// ---------------------------------------------------------------------------
// MMA / cp.async primitives
// ---------------------------------------------------------------------------
__device__ __forceinline__ void mma_tf32(float* d, const unsigned* a, const unsigned* b) {
    asm volatile(
        "mma.sync.aligned.m16n8k8.row.col.f32.tf32.tf32.f32 "
        "{%0,%1,%2,%3}, {%4,%5,%6,%7}, {%8,%9}, {%0,%1,%2,%3};\n"
        : "+f"(d[0]), "+f"(d[1]), "+f"(d[2]), "+f"(d[3])
        : "r"(a[0]), "r"(a[1]), "r"(a[2]), "r"(a[3]), "r"(b[0]), "r"(b[1]));
}
__device__ __forceinline__ void cpasync16(float* dst, const float* src) {
    unsigned saddr = (unsigned)__cvta_generic_to_shared(dst);
    asm volatile("cp.async.cg.shared.global [%0], [%1], 16;\n" :: "r"(saddr), "l"(src));
}
__device__ __forceinline__ float sigf(float x) { return 1.f / (1.f + __expf(-x)); }

// ===========================================================================
// Generic TF32 GEMM (128x128 tile, 4-stage cp.async) — precompute stage
// ===========================================================================
#define STAGE_F 4096

__global__ __launch_bounds__(256, 2)
void gemm_mma(const float* __restrict__ A, int lda,
              const float* __restrict__ Bw, int ldb,
              const float* __restrict__ bias,
              float* __restrict__ C, int ldc, int K, int round_out)
{
    cudaGridDependencySynchronize();
    extern __shared__ float sm[];
    int tid  = threadIdx.x;
    int lane = tid & 31;
    int warp = tid >> 5;
    int wm = (warp >> 2) * 64;
    int wn = (warp & 3) * 32;
    int g  = lane >> 2;
    int tg = lane & 3;
    int m0 = blockIdx.y * 128;
    int n0 = blockIdx.x * 128;

    int prow   = tid >> 2;
    int pchunk = (tid & 3) << 2;
    int psw    = ((prow >> 1) & 3) << 2;
    int dA = prow * 16 + (pchunk ^ psw);
    const float* Ag   = A  + (size_t)(m0 + prow) * lda + pchunk;
    const float* Ag64 = Ag + (size_t)64 * lda;
    const float* Bg   = Bw + (size_t)(n0 + prow) * ldb + pchunk;
    const float* Bg64 = Bg + (size_t)64 * ldb;

    auto prefetch = [&](int st, int k0) {
        float* sA = sm + st * STAGE_F;
        float* sB = sA + 2048;
        cpasync16(sA + dA,        Ag   + k0);
        cpasync16(sA + dA + 1024, Ag64 + k0);
        cpasync16(sB + dA,        Bg   + k0);
        cpasync16(sB + dA + 1024, Bg64 + k0);
        asm volatile("cp.async.commit_group;\n" ::);
    };

    float acc[4][4][4];
#pragma unroll
    for (int i = 0; i < 4; ++i)
#pragma unroll
        for (int j = 0; j < 4; ++j)
#pragma unroll
            for (int q = 0; q < 4; ++q) acc[i][j][q] = 0.f;

    int ktiles = K >> 4;
    prefetch(0, 0); prefetch(1, 16); prefetch(2, 32);
    int swz = ((g >> 1) & 3) << 2;

    for (int kt = 0; kt < ktiles; ++kt) {
        asm volatile("cp.async.wait_group 2;\n" ::);
        __syncthreads();
        if (kt + 3 < ktiles) prefetch((kt + 3) & 3, (kt + 3) << 4);
        else asm volatile("cp.async.commit_group;\n" ::);

        const unsigned* sA = (const unsigned*)(sm + (kt & 3) * STAGE_F);
        const unsigned* sB = sA + 2048;
        const unsigned* pA = sA + (wm + g) * 16;
        const unsigned* pB = sB + (wn + g) * 16;

#pragma unroll
        for (int ks = 0; ks < 2; ++ks) {
            int c0 = (ks * 8 + tg) ^ swz;
            int c4 = (ks * 8 + tg + 4) ^ swz;
            unsigned af[4][4], bf[4][2];
#pragma unroll
            for (int i = 0; i < 4; ++i) {
                af[i][0] = pA[i * 256 + c0];
                af[i][1] = pA[i * 256 + 128 + c0];
                af[i][2] = pA[i * 256 + c4];
                af[i][3] = pA[i * 256 + 128 + c4];
            }
#pragma unroll
            for (int j = 0; j < 4; ++j) {
                bf[j][0] = pB[j * 128 + c0];
                bf[j][1] = pB[j * 128 + c4];
            }
#pragma unroll
            for (int i = 0; i < 4; ++i)
#pragma unroll
                for (int j = 0; j < 4; ++j)
                    mma_tf32(acc[i][j], af[i], bf[j]);
        }
    }

#pragma unroll
    for (int i = 0; i < 4; ++i) {
        int r0 = m0 + wm + i * 16 + g;
#pragma unroll
        for (int j = 0; j < 4; ++j) {
            int c = n0 + wn + j * 8 + 2 * tg;
            float v0 = acc[i][j][0], v1 = acc[i][j][1];
            float v2 = acc[i][j][2], v3 = acc[i][j][3];
            if (bias) {
                float2 bb = *(const float2*)&bias[c];
                v0 += bb.x; v1 += bb.y; v2 += bb.x; v3 += bb.y;
            }
            if (round_out) {
                v0 = f2tff(v0); v1 = f2tff(v1); v2 = f2tff(v2); v3 = f2tff(v3);
            }
            *(float2*)&C[(size_t)r0 * ldc + c]       = make_float2(v0, v1);
            *(float2*)&C[(size_t)(r0 + 8) * ldc + c] = make_float2(v2, v3);
        }
    }
}

// ===========================================================================
// Persistent scan kernel: all 47 steps in one launch, grid (12,12) = 144 CTAs.
// Cross-CTA data (g, ht) goes through L2 ONLY (cp.async.cg / __ldcg).
// ===========================================================================
__device__ __forceinline__ void gbar(unsigned& bars) {
    __syncthreads();
    if (threadIdx.x == 0) {
        __threadfence();                       // release
        atomicAdd(&d_barcnt, 1u);
        unsigned target = (++bars) * NBLK;
        while (atomicAdd(&d_barcnt, 0u) < target) __nanosleep(64);
        __threadfence();                       // acquire
    }
    __syncthreads();
}

// Gate for one (m, 4-channel) item. g and hin read via L2 (__ldcg).
__device__ __forceinline__ void gate_item(
    int idx, const float* __restrict__ g, const float* __restrict__ hin,
    float* __restrict__ hout, const float* __restrict__ Bias,
    float* __restrict__ out_all, float* __restrict__ out_col,
    float* __restrict__ out_row, int s)
{
    int c = idx & 63;
    int m = idx >> 6;
    int b = m & 63;
    int r = m >> 6;

    const float4* G = (const float4*)(g + (size_t)m * 1536);
    float4 q[6];
#pragma unroll
    for (int t = 0; t < 6; ++t) q[t] = __ldcg(&G[c + t * 64]);
    if (r <= s && s < RR) {
        const float4* B4 = (const float4*)Bias;
#pragma unroll
        for (int t = 0; t < 6; ++t) {
            float4 bb = B4[c + t * 64];
            q[t].x += bb.x; q[t].y += bb.y; q[t].z += bb.z; q[t].w += bb.w;
        }
    }
    float* qa = (float*)q;
    float4 hro = __ldcg((const float4*)(hin + (size_t)m * 512) + c);
    float4 hco = __ldcg((const float4*)(hin + (size_t)m * 512 + 256) + c);
    float* hrp = (float*)&hro;
    float* hcp = (float*)&hco;
    float hr[4], hc[4];
#pragma unroll
    for (int t = 0; t < 4; ++t) {
        float ug_r = sigf(qa[t]);
        float og_r = sigf(qa[4 + t]);
        float ug_c = sigf(qa[8 + t]);
        float og_c = sigf(qa[12 + t]);
        float ig_r = tanhf(qa[16 + t]);
        float ig_c = tanhf(qa[20 + t]);
        hr[t] = tanhf((1.f - ug_r) * hrp[t] + ug_r * ig_r) * og_r;
        hc[t] = tanhf((1.f - ug_c) * hcp[t] + ug_c * ig_c) * og_c;
    }
    float4 hr4 = make_float4(hr[0], hr[1], hr[2], hr[3]);
    float4 hc4 = make_float4(hc[0], hc[1], hc[2], hc[3]);

    int r2 = (r + 1) % RR;
    int mc = r2 * BB + b;
    ((float4*)(hout + (size_t)m * 512))[c]        = tf4(hr4);
    ((float4*)(hout + (size_t)mc * 512 + 256))[c] = tf4(hc4);

    float* ob = out_all + ((size_t)m * LSTEPS + s) * 512;
    ((float4*)ob)[c]         = hr4;
    ((float4*)(ob + 256))[c] = hc4;

    if (s >= OO - 1) {
        int t2 = s - (OO - 1);
        if (r == t2)      ((float4*)(out_row + (size_t)(b * RR + t2) * HH))[c] = hr4;
        if (r == RR - 1)  ((float4*)(out_col + (size_t)(b * OO + t2) * HH))[c] = hc4;
    }
}

// GEMM phase for one step: g = hin @ Wt[:, :512]ᵀ + preS  (lda=512, ldb=768)
__device__ __forceinline__ void gemm_phase(
    const float* __restrict__ A, const float* __restrict__ Bw,
    const float* __restrict__ preS, float* __restrict__ C, float* sm)
{
    int tid  = threadIdx.x;
    int lane = tid & 31;
    int warp = tid >> 5;
    int wm = (warp >> 2) * 64;
    int wn = (warp & 3) * 32;
    int g  = lane >> 2;
    int tg = lane & 3;
    int m0 = blockIdx.y * 128;
    int n0 = blockIdx.x * 128;

    int prow   = tid >> 2;
    int pchunk = (tid & 3) << 2;
    int psw    = ((prow >> 1) & 3) << 2;
    int dA = prow * 16 + (pchunk ^ psw);
    const float* Ag   = A  + (size_t)(m0 + prow) * 512 + pchunk;
    const float* Ag64 = Ag + (size_t)64 * 512;
    const float* Bg   = Bw + (size_t)(n0 + prow) * 768 + pchunk;
    const float* Bg64 = Bg + (size_t)64 * 768;

    auto prefetch = [&](int st, int k0) {
        float* sA = sm + st * STAGE_F;
        float* sB = sA + 2048;
        cpasync16(sA + dA,        Ag   + k0);
        cpasync16(sA + dA + 1024, Ag64 + k0);
        cpasync16(sB + dA,        Bg   + k0);
        cpasync16(sB + dA + 1024, Bg64 + k0);
        asm volatile("cp.async.commit_group;\n" ::);
    };

    float acc[4][4][4];
#pragma unroll
    for (int i = 0; i < 4; ++i)
#pragma unroll
        for (int j = 0; j < 4; ++j)
#pragma unroll
            for (int q = 0; q < 4; ++q) acc[i][j][q] = 0.f;

    prefetch(0, 0); prefetch(1, 16); prefetch(2, 32);
    int swz = ((g >> 1) & 3) << 2;

    for (int kt = 0; kt < 32; ++kt) {
        asm volatile("cp.async.wait_group 2;\n" ::);
        __syncthreads();
        if (kt + 3 < 32) prefetch((kt + 3) & 3, (kt + 3) << 4);
        else asm volatile("cp.async.commit_group;\n" ::);

        const unsigned* sA = (const unsigned*)(sm + (kt & 3) * STAGE_F);
        const unsigned* sB = sA + 2048;
        const unsigned* pA = sA + (wm + g) * 16;
        const unsigned* pB = sB + (wn + g) * 16;

#pragma unroll
        for (int ks = 0; ks < 2; ++ks) {
            int c0 = (ks * 8 + tg) ^ swz;
            int c4 = (ks * 8 + tg + 4) ^ swz;
            unsigned af[4][4], bf[4][2];
#pragma unroll
            for (int i = 0; i < 4; ++i) {
                af[i][0] = pA[i * 256 + c0];
                af[i][1] = pA[i * 256 + 128 + c0];
                af[i][2] = pA[i * 256 + c4];
                af[i][3] = pA[i * 256 + 128 + c4];
            }
#pragma unroll
            for (int j = 0; j < 4; ++j) {
                bf[j][0] = pB[j * 128 + c0];
                bf[j][1] = pB[j * 128 + c4];
            }
#pragma unroll
            for (int i = 0; i < 4; ++i)
#pragma unroll
                for (int j = 0; j < 4; ++j)
                    mma_tf32(acc[i][j], af[i], bf[j]);
        }
    }

#pragma unroll
    for (int i = 0; i < 4; ++i) {
        int r0 = m0 + wm + i * 16 + g;
#pragma unroll
        for (int j = 0; j < 4; ++j) {
            int c = n0 + wn + j * 8 + 2 * tg;
            float2 p0 = __ldcg((const float2*)&preS[(size_t)r0 * 1536 + c]);
            float2 p1 = __ldcg((const float2*)&preS[(size_t)(r0 + 8) * 1536 + c]);
            *(float2*)&C[(size_t)r0 * 1536 + c] =
                make_float2(acc[i][j][0] + p0.x, acc[i][j][1] + p0.y);
            *(float2*)&C[(size_t)(r0 + 8) * 1536 + c] =
                make_float2(acc[i][j][2] + p1.x, acc[i][j][3] + p1.y);
        }
    }
}

__global__ __launch_bounds__(256)
void scan_persist(const float* __restrict__ Wt, const float* __restrict__ pre,
                  const float* __restrict__ Bias, float* __restrict__ ht,
                  float* __restrict__ g,
                  float* __restrict__ out_all, float* __restrict__ out_col,
                  float* __restrict__ out_row)
{
    cudaGridDependencySynchronize();
    extern __shared__ float sm[];
    int bid = blockIdx.y * gridDim.x + blockIdx.x;
    int tbase = bid * 256 + threadIdx.x;
    unsigned bars = 0;

    // s = 0: h == 0 -> g == pre[0]; gate directly
    for (int idx = tbase; idx < M1 * 64; idx += NBLK * 256)
        gate_item(idx, pre, ht, ht + (size_t)M1 * 512, Bias,
                  out_all, out_col, out_row, 0);
    gbar(bars);

    for (int s = 1; s < LSTEPS; ++s) {
        const float* hin = ht + (size_t)(s & 1) * M1 * 512;
        float* hout      = ht + (size_t)((s + 1) & 1) * M1 * 512;
        gemm_phase(hin, Wt, pre + (size_t)s * M1 * 1536, g, sm);
        gbar(bars);
        for (int idx = tbase; idx < M1 * 64; idx += NBLK * 256)
            gate_item(idx, g, hin, hout, Bias, out_all, out_col, out_row, s);
        gbar(bars);
    }
}

// ---------------------------------------------------------------------------
// MHA core per (l, b, h)
// ---------------------------------------------------------------------------
__global__ __launch_bounds__(768)
void attn_kernel(const float* __restrict__ qkv, const float* __restrict__ mask,
                 float* __restrict__ att) {
    cudaGridDependencySynchronize();
    int bid = blockIdx.x;
    int h = bid & 1;
    int b = (bid >> 1) & 63;
    int l = bid >> 7;

    __shared__ float ks[RR][64];
    __shared__ float vs[RR][64];
    int tid = threadIdx.x;
    for (int idx = tid; idx < RR * 64; idx += 768) {
        int s = idx >> 6, d = idx & 63;
        int base = ((l * RR + s) * BB + b) * 384 + h * 64 + d;
        ks[s][d] = qkv[base + 128];
        vs[s][d] = qkv[base + 256];
    }
    __syncthreads();

    int w = tid >> 5, lane = tid & 31;
    if (w >= RR) return;
    int r = w;
    int mq = ((l * RR + r) * BB + b) * 384 + h * 64;
    float q0 = qkv[mq + lane];
    float q1 = qkv[mq + 32 + lane];

    float sc = 0.f;
#pragma unroll
    for (int s = 0; s < RR; ++s) {
        float part = q0 * ks[s][lane] + q1 * ks[s][lane + 32];
#pragma unroll
        for (int off = 16; off; off >>= 1)
            part += __shfl_xor_sync(0xffffffffu, part, off);
        if (lane == s) sc = part;
    }
    float sco = (lane < RR) ? sc * 0.125f + mask[r * RR + lane] : -INFINITY;
    float mx = sco;
#pragma unroll
    for (int off = 16; off; off >>= 1)
        mx = fmaxf(mx, __shfl_xor_sync(0xffffffffu, mx, off));
    float e = expf(sco - mx);
    float sum = e;
#pragma unroll
    for (int off = 16; off; off >>= 1)
        sum += __shfl_xor_sync(0xffffffffu, sum, off);
    float p = e / sum;

    float acc0 = 0.f, acc1 = 0.f;
#pragma unroll
    for (int s = 0; s < RR; ++s) {
        float ps = __shfl_sync(0xffffffffu, p, s);
        acc0 = fmaf(ps, vs[s][lane], acc0);
        acc1 = fmaf(ps, vs[s][lane + 32], acc1);
    }
    int mo = ((l * RR + r) * BB + b) * EMB + h * 64;
    att[mo + lane]      = f2tff(acc0);
    att[mo + 32 + lane] = f2tff(acc1);
}

// ---------------------------------------------------------------------------
// Launch
// ---------------------------------------------------------------------------
extern "C" void kernel_launch(void* const* d_in, const int* in_sizes, int n_in,
                              void* d_out, int out_size) {
    const float* input = (const float*)d_in[0];
    const float* mask  = (const float*)d_in[1];
    const float* W     = (const float*)d_in[2];
    const float* Bias  = (const float*)d_in[3];
    const float* inw   = (const float*)d_in[4];
    const float* inb   = (const float*)d_in[5];
    const float* outw  = (const float*)d_in[6];
    const float* outb  = (const float*)d_in[7];
    float* out = (float*)d_out;

    float *xy, *qkv, *att, *pre, *ht, *g, *Wt, *inwt, *outwt;
    unsigned* barcnt;
    cudaGetSymbolAddress((void**)&xy,    d_xy);
    cudaGetSymbolAddress((void**)&qkv,   d_qkv);
    cudaGetSymbolAddress((void**)&att,   d_att);
    cudaGetSymbolAddress((void**)&pre,   d_pre);
    cudaGetSymbolAddress((void**)&ht,    d_ht);
    cudaGetSymbolAddress((void**)&g,     d_g);
    cudaGetSymbolAddress((void**)&Wt,    d_Wt);
    cudaGetSymbolAddress((void**)&inwt,  d_inwt);
    cudaGetSymbolAddress((void**)&outwt, d_outwt);
    cudaGetSymbolAddress((void**)&barcnt, d_barcnt);

    cudaFuncSetAttribute(gemm_mma, cudaFuncAttributeMaxDynamicSharedMemorySize, 65536);
    cudaFuncSetAttribute(scan_persist, cudaFuncAttributeMaxDynamicSharedMemorySize, 65536);
    const int SMEMB = 65536;

    // memsets first so the PDL kernel chain below is unbroken
    cudaMemsetAsync(barcnt, 0, sizeof(unsigned));
    cudaMemsetAsync(ht, 0, (size_t)M1 * 512 * sizeof(float));

    // 0) one-time tf32 rounding of weights
    cvt_kernel<<<(1536 * 768 / 4 + 255) / 256, 256>>>(W, Wt, 1536 * 768 / 4);
    cvt_kernel<<<(384 * 128 / 4 + 255) / 256, 256>>>(inw, inwt, 384 * 128 / 4);
    cvt_kernel<<<(128 * 128 / 4 + 255) / 256, 256>>>(outw, outwt, 128 * 128 / 4);

    // 1) x (tf32)
    build_x_kernel<<<(MALL * 32 + 255) / 256, 256>>>(input, xy);

    // PDL config helper
    cudaLaunchAttribute pdlAttr[1];
    pdlAttr[0].id = cudaLaunchAttributeProgrammaticStreamSerialization;
    pdlAttr[0].val.programmaticStreamSerializationAllowed = 1;

    auto mkcfg = [&](dim3 grid, dim3 block, size_t smem) {
        cudaLaunchConfig_t c = {};
        c.gridDim = grid; c.blockDim = block; c.dynamicSmemBytes = smem;
        c.stream = 0; c.attrs = pdlAttr; c.numAttrs = 1;
        return c;
    };

    // 2) qkv = x @ in_proj_wᵀ + b
    {
        cudaLaunchConfig_t c = mkcfg(dim3(3, MALL / 128), dim3(256), SMEMB);
        cudaLaunchKernelEx(&c, gemm_mma, (const float*)xy, 256,
                           (const float*)inwt, EMB, inb, qkv, 384, EMB, 0);
    }
    // 3) attention
    {
        cudaLaunchConfig_t c = mkcfg(dim3(LSTEPS * BB * 2), dim3(768), 0);
        cudaLaunchKernelEx(&c, attn_kernel, (const float*)qkv, mask, att);
    }
    // 4) y = att @ out_proj_wᵀ + b -> xy[:,128:256] (tf32)
    {
        cudaLaunchConfig_t c = mkcfg(dim3(1, MALL / 128), dim3(256), SMEMB);
        cudaLaunchKernelEx(&c, gemm_mma, (const float*)att, EMB,
                           (const float*)outwt, EMB, outb, xy + 128, 256, EMB, 1);
    }
    // 5) pre = [x|y] @ W[:, 512:768]ᵀ
    {
        cudaLaunchConfig_t c = mkcfg(dim3(12, MALL / 128), dim3(256), SMEMB);
        cudaLaunchKernelEx(&c, gemm_mma, (const float*)xy, 256,
                           (const float*)(Wt + 512), 768, (const float*)nullptr,
                           pre, 1536, 256, 0);
    }
    // 6) persistent scan (all 47 steps)
    {
        cudaLaunchConfig_t c = mkcfg(dim3(12, 12), dim3(256), SMEMB);
        cudaLaunchKernelEx(&c, scan_persist, (const float*)Wt, (const float*)pre,
                           Bias, ht, g, out, out + OUT_ALL_ELEMS,
                           out + OUT_ALL_ELEMS + HID_ELEMS);
    }
}

// round 9
// speedup vs baseline: 1.1615x; 1.1615x over previous
#include <cuda_runtime.h>
#include <cmath>

// Problem constants
#define LSTEPS 47
#define RR 24
#define OO 24
#define BB 64
#define EMB 128
#define HH 256
#define M1 1536        // RR * BB
#define MALL 72192     // LSTEPS * M1

#define OUT_ALL_ELEMS 36962304   // M1 * LSTEPS * 512
#define HID_ELEMS 393216         // BB * 24 * HH

// Scratch
__device__ float d_xy[(size_t)MALL * 256];    // [x | y] packed tf32
__device__ float d_qkv[(size_t)MALL * 384];
__device__ float d_att[(size_t)MALL * 128];   // tf32-rounded
__device__ float d_pre[(size_t)MALL * 1536];
__device__ float d_ht[2 * M1 * 512];          // tf32 state ping-pong [h_row|h_col]
__device__ float d_g[M1 * 1536];
__device__ float d_Wt[1536 * 768];            // tf32-rounded W
__device__ float d_inwt[384 * 128];
__device__ float d_outwt[128 * 128];

__device__ __forceinline__ unsigned f2tf(float x) {
    unsigned u; asm("cvt.rna.tf32.f32 %0, %1;" : "=r"(u) : "f"(x)); return u;
}
__device__ __forceinline__ float f2tff(float x) { return __uint_as_float(f2tf(x)); }
__device__ __forceinline__ float4 tf4(float4 v) {
    return make_float4(f2tff(v.x), f2tff(v.y), f2tff(v.z), f2tff(v.w));
}
__device__ __forceinline__ float tanha(float x) {
    float y; asm("tanh.approx.f32 %0, %1;" : "=f"(y) : "f"(x)); return y;
}

// ---------------------------------------------------------------------------
// Fused one-time weight conversion: W (294912 f4), inw (12288 f4), outw (4096 f4)
// ---------------------------------------------------------------------------
#define W4   294912
#define IW4  12288
#define OW4  4096
__global__ void cvt_all_kernel(const float* __restrict__ W, float* __restrict__ Wt,
                               const float* __restrict__ inw, float* __restrict__ inwt,
                               const float* __restrict__ outw, float* __restrict__ outwt) {
    int i = blockIdx.x * 256 + threadIdx.x;
    if (i < W4) {
        ((float4*)Wt)[i] = tf4(((const float4*)W)[i]);
    } else if (i < W4 + IW4) {
        int j = i - W4;
        ((float4*)inwt)[j] = tf4(((const float4*)inw)[j]);
    } else if (i < W4 + IW4 + OW4) {
        int j = i - W4 - IW4;
        ((float4*)outwt)[j] = tf4(((const float4*)outw)[j]);
    }
}

// ---------------------------------------------------------------------------
// build x (tf32): xy[m*256 + i] = input[b, l-r, r, i] (zero outside)
// ---------------------------------------------------------------------------
__global__ void build_x_kernel(const float* __restrict__ input, float* __restrict__ xy) {
    int idx = blockIdx.x * 256 + threadIdx.x;
    if (idx >= MALL * 32) return;
    int c = idx & 31;
    int m = idx >> 5;
    int b = m & 63;
    int t = m >> 6;
    int r = t % RR;
    int l = t / RR;
    int o = l - r;
    float4 v = make_float4(0.f, 0.f, 0.f, 0.f);
    if (o >= 0 && o < OO)
        v = tf4(((const float4*)(input + (size_t)((b * OO + o) * RR + r) * EMB))[c]);
    ((float4*)(xy + (size_t)m * 256))[c] = v;
}

// ---------------------------------------------------------------------------
// MMA / cp.async primitives
// ---------------------------------------------------------------------------
__device__ __forceinline__ void mma_tf32(float* d, const unsigned* a, const unsigned* b) {
    asm volatile(
        "mma.sync.aligned.m16n8k8.row.col.f32.tf32.tf32.f32 "
        "{%0,%1,%2,%3}, {%4,%5,%6,%7}, {%8,%9}, {%0,%1,%2,%3};\n"
        : "+f"(d[0]), "+f"(d[1]), "+f"(d[2]), "+f"(d[3])
        : "r"(a[0]), "r"(a[1]), "r"(a[2]), "r"(a[3]), "r"(b[0]), "r"(b[1]));
}
__device__ __forceinline__ void cpasync16(float* dst, const float* src) {
    unsigned saddr = (unsigned)__cvta_generic_to_shared(dst);
    asm volatile("cp.async.cg.shared.global [%0], [%1], 16;\n" :: "r"(saddr), "l"(src));
}
__device__ __forceinline__ float sigf(float x) { return 1.f / (1.f + __expf(-x)); }

// ===========================================================================
// Generic TF32 GEMM (128x128 tile, 4-stage cp.async).
// C = A @ Bwᵀ (+Cinit)(+bias)(round). Used for precompute AND scan steps.
// ===========================================================================
#define STAGE_F 4096

__global__ __launch_bounds__(256, 2)
void gemm_mma(const float* __restrict__ A, int lda,
              const float* __restrict__ Bw, int ldb,
              const float* __restrict__ bias,
              const float* __restrict__ Cinit,
              float* __restrict__ C, int ldc, int K, int round_out)
{
    cudaGridDependencySynchronize();   // no-op unless launched with PDL attr
    extern __shared__ float sm[];
    int tid  = threadIdx.x;
    int lane = tid & 31;
    int warp = tid >> 5;
    int wm = (warp >> 2) * 64;
    int wn = (warp & 3) * 32;
    int g  = lane >> 2;
    int tg = lane & 3;
    int m0 = blockIdx.y * 128;
    int n0 = blockIdx.x * 128;

    int prow   = tid >> 2;
    int pchunk = (tid & 3) << 2;
    int psw    = ((prow >> 1) & 3) << 2;
    int dA = prow * 16 + (pchunk ^ psw);
    const float* Ag   = A  + (size_t)(m0 + prow) * lda + pchunk;
    const float* Ag64 = Ag + (size_t)64 * lda;
    const float* Bg   = Bw + (size_t)(n0 + prow) * ldb + pchunk;
    const float* Bg64 = Bg + (size_t)64 * ldb;

    auto prefetch = [&](int st, int k0) {
        float* sA = sm + st * STAGE_F;
        float* sB = sA + 2048;
        cpasync16(sA + dA,        Ag   + k0);
        cpasync16(sA + dA + 1024, Ag64 + k0);
        cpasync16(sB + dA,        Bg   + k0);
        cpasync16(sB + dA + 1024, Bg64 + k0);
        asm volatile("cp.async.commit_group;\n" ::);
    };

    float acc[4][4][4];
#pragma unroll
    for (int i = 0; i < 4; ++i)
#pragma unroll
        for (int j = 0; j < 4; ++j)
#pragma unroll
            for (int q = 0; q < 4; ++q) acc[i][j][q] = 0.f;

    int ktiles = K >> 4;
    prefetch(0, 0); prefetch(1, 16); prefetch(2, 32);
    int swz = ((g >> 1) & 3) << 2;

    for (int kt = 0; kt < ktiles; ++kt) {
        asm volatile("cp.async.wait_group 2;\n" ::);
        __syncthreads();
        if (kt + 3 < ktiles) prefetch((kt + 3) & 3, (kt + 3) << 4);
        else asm volatile("cp.async.commit_group;\n" ::);

        const unsigned* sA = (const unsigned*)(sm + (kt & 3) * STAGE_F);
        const unsigned* sB = sA + 2048;
        const unsigned* pA = sA + (wm + g) * 16;
        const unsigned* pB = sB + (wn + g) * 16;

#pragma unroll
        for (int ks = 0; ks < 2; ++ks) {
            int c0 = (ks * 8 + tg) ^ swz;
            int c4 = (ks * 8 + tg + 4) ^ swz;
            unsigned af[4][4], bf[4][2];
#pragma unroll
            for (int i = 0; i < 4; ++i) {
                af[i][0] = pA[i * 256 + c0];
                af[i][1] = pA[i * 256 + 128 + c0];
                af[i][2] = pA[i * 256 + c4];
                af[i][3] = pA[i * 256 + 128 + c4];
            }
#pragma unroll
            for (int j = 0; j < 4; ++j) {
                bf[j][0] = pB[j * 128 + c0];
                bf[j][1] = pB[j * 128 + c4];
            }
#pragma unroll
            for (int i = 0; i < 4; ++i)
#pragma unroll
                for (int j = 0; j < 4; ++j)
                    mma_tf32(acc[i][j], af[i], bf[j]);
        }
    }

#pragma unroll
    for (int i = 0; i < 4; ++i) {
        int r0 = m0 + wm + i * 16 + g;
#pragma unroll
        for (int j = 0; j < 4; ++j) {
            int c = n0 + wn + j * 8 + 2 * tg;
            float v0 = acc[i][j][0], v1 = acc[i][j][1];
            float v2 = acc[i][j][2], v3 = acc[i][j][3];
            if (Cinit) {
                float2 p0 = *(const float2*)&Cinit[(size_t)r0 * ldc + c];
                float2 p1 = *(const float2*)&Cinit[(size_t)(r0 + 8) * ldc + c];
                v0 += p0.x; v1 += p0.y; v2 += p1.x; v3 += p1.y;
            }
            if (bias) {
                float2 bb = *(const float2*)&bias[c];
                v0 += bb.x; v1 += bb.y; v2 += bb.x; v3 += bb.y;
            }
            if (round_out) {
                v0 = f2tff(v0); v1 = f2tff(v1); v2 = f2tff(v2); v3 = f2tff(v3);
            }
            *(float2*)&C[(size_t)r0 * ldc + c]       = make_float2(v0, v1);
            *(float2*)&C[(size_t)(r0 + 8) * ldc + c] = make_float2(v2, v3);
        }
    }
}

// ---------------------------------------------------------------------------
// MHA core per (l, b, h)
// ---------------------------------------------------------------------------
__global__ __launch_bounds__(768)
void attn_kernel(const float* __restrict__ qkv, const float* __restrict__ mask,
                 float* __restrict__ att) {
    cudaGridDependencySynchronize();
    int bid = blockIdx.x;
    int h = bid & 1;
    int b = (bid >> 1) & 63;
    int l = bid >> 7;

    __shared__ float ks[RR][64];
    __shared__ float vs[RR][64];
    int tid = threadIdx.x;
    for (int idx = tid; idx < RR * 64; idx += 768) {
        int s = idx >> 6, d = idx & 63;
        int base = ((l * RR + s) * BB + b) * 384 + h * 64 + d;
        ks[s][d] = qkv[base + 128];
        vs[s][d] = qkv[base + 256];
    }
    __syncthreads();

    int w = tid >> 5, lane = tid & 31;
    if (w >= RR) return;
    int r = w;
    int mq = ((l * RR + r) * BB + b) * 384 + h * 64;
    float q0 = qkv[mq + lane];
    float q1 = qkv[mq + 32 + lane];

    float sc = 0.f;
#pragma unroll
    for (int s = 0; s < RR; ++s) {
        float part = q0 * ks[s][lane] + q1 * ks[s][lane + 32];
#pragma unroll
        for (int off = 16; off; off >>= 1)
            part += __shfl_xor_sync(0xffffffffu, part, off);
        if (lane == s) sc = part;
    }
    float sco = (lane < RR) ? sc * 0.125f + mask[r * RR + lane] : -INFINITY;
    float mx = sco;
#pragma unroll
    for (int off = 16; off; off >>= 1)
        mx = fmaxf(mx, __shfl_xor_sync(0xffffffffu, mx, off));
    float e = expf(sco - mx);
    float sum = e;
#pragma unroll
    for (int off = 16; off; off >>= 1)
        sum += __shfl_xor_sync(0xffffffffu, sum, off);
    float p = e / sum;

    float acc0 = 0.f, acc1 = 0.f;
#pragma unroll
    for (int s = 0; s < RR; ++s) {
        float ps = __shfl_sync(0xffffffffu, p, s);
        acc0 = fmaf(ps, vs[s][lane], acc0);
        acc1 = fmaf(ps, vs[s][lane + 32], acc1);
    }
    int mo = ((l * RR + r) * BB + b) * EMB + h * 64;
    att[mo + lane]      = f2tff(acc0);
    att[mo + 32 + lane] = f2tff(acc1);
}

// ---------------------------------------------------------------------------
// Gate / state update / outputs (float4; tf32 state; MUFU tanh/sigmoid;
// streaming stores for out_all)
// ---------------------------------------------------------------------------
__global__ __launch_bounds__(256)
void gate_kernel(const float* __restrict__ g,
                 const float* __restrict__ hin,
                 float* __restrict__ hout,
                 const float* __restrict__ Bias,
                 float* __restrict__ out_all,
                 float* __restrict__ out_col,
                 float* __restrict__ out_row,
                 int s) {
    cudaGridDependencySynchronize();
    int idx = blockIdx.x * 256 + threadIdx.x;   // M1*HH/4 = 98304
    int c = idx & 63;
    int m = idx >> 6;
    int b = m & 63;
    int r = m >> 6;

    const float4* G = (const float4*)(g + (size_t)m * 1536);
    float4 q[6];
#pragma unroll
    for (int t = 0; t < 6; ++t) q[t] = G[c + t * 64];
    if (r <= s && s < RR) {
        const float4* B4 = (const float4*)Bias;
#pragma unroll
        for (int t = 0; t < 6; ++t) {
            float4 bb = B4[c + t * 64];
            q[t].x += bb.x; q[t].y += bb.y; q[t].z += bb.z; q[t].w += bb.w;
        }
    }
    float* qa = (float*)q;
    float4 hro = ((const float4*)(hin + (size_t)m * 512))[c];
    float4 hco = ((const float4*)(hin + (size_t)m * 512 + 256))[c];
    float* hrp = (float*)&hro;
    float* hcp = (float*)&hco;
    float hr[4], hc[4];
#pragma unroll
    for (int t = 0; t < 4; ++t) {
        float ug_r = sigf(qa[t]);
        float og_r = sigf(qa[4 + t]);
        float ug_c = sigf(qa[8 + t]);
        float og_c = sigf(qa[12 + t]);
        float ig_r = tanha(qa[16 + t]);
        float ig_c = tanha(qa[20 + t]);
        hr[t] = tanha((1.f - ug_r) * hrp[t] + ug_r * ig_r) * og_r;
        hc[t] = tanha((1.f - ug_c) * hcp[t] + ug_c * ig_c) * og_c;
    }
    float4 hr4 = make_float4(hr[0], hr[1], hr[2], hr[3]);
    float4 hc4 = make_float4(hc[0], hc[1], hc[2], hc[3]);

    int r2 = (r + 1) % RR;
    int mc = r2 * BB + b;
    ((float4*)(hout + (size_t)m * 512))[c]        = tf4(hr4);
    ((float4*)(hout + (size_t)mc * 512 + 256))[c] = tf4(hc4);

    float* ob = out_all + ((size_t)m * LSTEPS + s) * 512;
    __stcs((float4*)ob + c, hr4);
    __stcs((float4*)(ob + 256) + c, hc4);

    if (s >= OO - 1) {
        int t2 = s - (OO - 1);
        if (r == t2)      ((float4*)(out_row + (size_t)(b * RR + t2) * HH))[c] = hr4;
        if (r == RR - 1)  ((float4*)(out_col + (size_t)(b * OO + t2) * HH))[c] = hc4;
    }
}

// ---------------------------------------------------------------------------
// Launch
// ---------------------------------------------------------------------------
extern "C" void kernel_launch(void* const* d_in, const int* in_sizes, int n_in,
                              void* d_out, int out_size) {
    const float* input = (const float*)d_in[0];
    const float* mask  = (const float*)d_in[1];
    const float* W     = (const float*)d_in[2];
    const float* Bias  = (const float*)d_in[3];
    const float* inw   = (const float*)d_in[4];
    const float* inb   = (const float*)d_in[5];
    const float* outw  = (const float*)d_in[6];
    const float* outb  = (const float*)d_in[7];
    float* out = (float*)d_out;

    float *xy, *qkv, *att, *pre, *ht, *g, *Wt, *inwt, *outwt;
    cudaGetSymbolAddress((void**)&xy,    d_xy);
    cudaGetSymbolAddress((void**)&qkv,   d_qkv);
    cudaGetSymbolAddress((void**)&att,   d_att);
    cudaGetSymbolAddress((void**)&pre,   d_pre);
    cudaGetSymbolAddress((void**)&ht,    d_ht);
    cudaGetSymbolAddress((void**)&g,     d_g);
    cudaGetSymbolAddress((void**)&Wt,    d_Wt);
    cudaGetSymbolAddress((void**)&inwt,  d_inwt);
    cudaGetSymbolAddress((void**)&outwt, d_outwt);

    cudaFuncSetAttribute(gemm_mma, cudaFuncAttributeMaxDynamicSharedMemorySize, 65536);
    const int SMEMB = 65536;

    // 0) one-time tf32 rounding of weights (fused single launch)
    cvt_all_kernel<<<(W4 + IW4 + OW4 + 255) / 256, 256>>>(W, Wt, inw, inwt, outw, outwt);

    // 1) x (tf32)
    build_x_kernel<<<(MALL * 32 + 255) / 256, 256>>>(input, xy);

    // 2) qkv = x @ in_proj_wᵀ + b
    gemm_mma<<<dim3(3, MALL / 128), 256, SMEMB>>>(xy, 256, inwt, EMB, inb, nullptr,
                                                  qkv, 384, EMB, 0);

    // 3) attention
    attn_kernel<<<LSTEPS * BB * 2, 768>>>(qkv, mask, att);

    // 4) y = att @ out_proj_wᵀ + b -> xy[:,128:256] (tf32)
    gemm_mma<<<dim3(1, MALL / 128), 256, SMEMB>>>(att, EMB, outwt, EMB, outb, nullptr,
                                                  xy + 128, 256, EMB, 1);

    // 5) pre = [x|y] @ W[:, 512:768]ᵀ
    gemm_mma<<<dim3(12, MALL / 128), 256, SMEMB>>>(xy, 256, Wt + 512, 768, nullptr,
                                                   nullptr, pre, 1536, 256, 0);

    // 6) zero initial state (buffer 0)
    cudaMemsetAsync(ht, 0, (size_t)M1 * 512 * sizeof(float));

    // PDL launch configs for the scan loop
    cudaLaunchAttribute pdlAttr[1];
    pdlAttr[0].id = cudaLaunchAttributeProgrammaticStreamSerialization;
    pdlAttr[0].val.programmaticStreamSerializationAllowed = 1;

    cudaLaunchConfig_t cfgGemm = {};
    cfgGemm.gridDim  = dim3(12, 12);
    cfgGemm.blockDim = dim3(256);
    cfgGemm.dynamicSmemBytes = SMEMB;
    cfgGemm.stream = 0;
    cfgGemm.attrs = pdlAttr;
    cfgGemm.numAttrs = 1;

    cudaLaunchConfig_t cfgGate = {};
    cfgGate.gridDim  = dim3(384);
    cfgGate.blockDim = dim3(256);
    cfgGate.dynamicSmemBytes = 0;
    cfgGate.stream = 0;
    cfgGate.attrs = pdlAttr;
    cfgGate.numAttrs = 1;

    float* out_col = out + OUT_ALL_ELEMS;
    float* out_row = out + OUT_ALL_ELEMS + HID_ELEMS;

    // 7) sequential scan; s=0 skips the GEMM (h == 0 -> g == pre[0])
    gate_kernel<<<384, 256>>>(pre, ht, ht + (size_t)M1 * 512, Bias,
                              out, out_col, out_row, 0);
    for (int s = 1; s < LSTEPS; ++s) {
        const float* hin = ht + (size_t)(s & 1) * M1 * 512;
        float* hout      = ht + (size_t)((s + 1) & 1) * M1 * 512;
        cudaLaunchKernelEx(&cfgGemm, gemm_mma,
                           (const float*)hin, 512, (const float*)Wt, 768,
                           (const float*)nullptr,
                           (const float*)(pre + (size_t)s * M1 * 1536),
                           g, 1536, 512, 0);
        cudaLaunchKernelEx(&cfgGate, gate_kernel,
                           (const float*)g, (const float*)hin, hout,
                           Bias, out, out_col, out_row, s);
    }
}

// round 10
// speedup vs baseline: 1.2147x; 1.0459x over previous
#include <cuda_runtime.h>
#include <cmath>

// Problem constants
#define LSTEPS 47
#define RR 24
#define OO 24
#define BB 64
#define EMB 128
#define HH 256
#define M1 1536        // RR * BB
#define MALL 72192     // LSTEPS * M1

#define OUT_ALL_ELEMS 36962304   // M1 * LSTEPS * 512
#define HID_ELEMS 393216         // BB * 24 * HH

// Scratch
__device__ float d_xy[(size_t)MALL * 256];    // [x | y] packed tf32
__device__ float d_qkv[(size_t)MALL * 384];
__device__ float d_att[(size_t)MALL * 128];   // tf32-rounded
__device__ float d_pre[(size_t)MALL * 1536];
__device__ float d_ht[2 * M1 * 512];          // tf32 state ping-pong [h_row|h_col]
__device__ float d_g[2 * (size_t)M1 * 1536];  // split-K partial sums (2 halves)
__device__ float d_Wt[1536 * 768];            // tf32-rounded W
__device__ float d_inwt[384 * 128];
__device__ float d_outwt[128 * 128];

__device__ __forceinline__ unsigned f2tf(float x) {
    unsigned u; asm("cvt.rna.tf32.f32 %0, %1;" : "=r"(u) : "f"(x)); return u;
}
__device__ __forceinline__ float f2tff(float x) { return __uint_as_float(f2tf(x)); }
__device__ __forceinline__ float4 tf4(float4 v) {
    return make_float4(f2tff(v.x), f2tff(v.y), f2tff(v.z), f2tff(v.w));
}
__device__ __forceinline__ float tanha(float x) {
    float y; asm("tanh.approx.f32 %0, %1;" : "=f"(y) : "f"(x)); return y;
}

// ---------------------------------------------------------------------------
// Fused one-time weight conversion
// ---------------------------------------------------------------------------
#define W4   294912
#define IW4  12288
#define OW4  4096
__global__ void cvt_all_kernel(const float* __restrict__ W, float* __restrict__ Wt,
                               const float* __restrict__ inw, float* __restrict__ inwt,
                               const float* __restrict__ outw, float* __restrict__ outwt) {
    int i = blockIdx.x * 256 + threadIdx.x;
    if (i < W4) {
        ((float4*)Wt)[i] = tf4(((const float4*)W)[i]);
    } else if (i < W4 + IW4) {
        int j = i - W4;
        ((float4*)inwt)[j] = tf4(((const float4*)inw)[j]);
    } else if (i < W4 + IW4 + OW4) {
        int j = i - W4 - IW4;
        ((float4*)outwt)[j] = tf4(((const float4*)outw)[j]);
    }
}

// ---------------------------------------------------------------------------
// build x (tf32): xy[m*256 + i] = input[b, l-r, r, i] (zero outside)
// ---------------------------------------------------------------------------
__global__ void build_x_kernel(const float* __restrict__ input, float* __restrict__ xy) {
    int idx = blockIdx.x * 256 + threadIdx.x;
    if (idx >= MALL * 32) return;
    int c = idx & 31;
    int m = idx >> 5;
    int b = m & 63;
    int t = m >> 6;
    int r = t % RR;
    int l = t / RR;
    int o = l - r;
    float4 v = make_float4(0.f, 0.f, 0.f, 0.f);
    if (o >= 0 && o < OO)
        v = tf4(((const float4*)(input + (size_t)((b * OO + o) * RR + r) * EMB))[c]);
    ((float4*)(xy + (size_t)m * 256))[c] = v;
}

// ---------------------------------------------------------------------------
// MMA / cp.async primitives
// ---------------------------------------------------------------------------
__device__ __forceinline__ void mma_tf32(float* d, const unsigned* a, const unsigned* b) {
    asm volatile(
        "mma.sync.aligned.m16n8k8.row.col.f32.tf32.tf32.f32 "
        "{%0,%1,%2,%3}, {%4,%5,%6,%7}, {%8,%9}, {%0,%1,%2,%3};\n"
        : "+f"(d[0]), "+f"(d[1]), "+f"(d[2]), "+f"(d[3])
        : "r"(a[0]), "r"(a[1]), "r"(a[2]), "r"(a[3]), "r"(b[0]), "r"(b[1]));
}
__device__ __forceinline__ void cpasync16(float* dst, const float* src) {
    unsigned saddr = (unsigned)__cvta_generic_to_shared(dst);
    asm volatile("cp.async.cg.shared.global [%0], [%1], 16;\n" :: "r"(saddr), "l"(src));
}
__device__ __forceinline__ float sigf(float x) { return 1.f / (1.f + __expf(-x)); }

// ===========================================================================
// Generic TF32 GEMM (128x128 tile, 4-stage cp.async).
// C = A @ Bwᵀ (+Cinit)(+bias)(round). ksplit: if grid.z>1, blockIdx.z picks a
// K-slice (A/Bw advanced by z*ksplit; C advanced by z*M1*ldc; Cinit only z=0).
// ===========================================================================
#define STAGE_F 4096

__global__ __launch_bounds__(256, 2)
void gemm_mma(const float* __restrict__ A, int lda,
              const float* __restrict__ Bw, int ldb,
              const float* __restrict__ bias,
              const float* __restrict__ Cinit,
              float* __restrict__ C, int ldc, int K, int round_out, int ksplit)
{
    cudaGridDependencySynchronize();   // no-op unless launched with PDL attr
    extern __shared__ float sm[];
    int kh = blockIdx.z;
    if (kh) {
        A += kh * ksplit;
        Bw += kh * ksplit;
        C += (size_t)kh * M1 * ldc;
        Cinit = nullptr;
    }
    int tid  = threadIdx.x;
    int lane = tid & 31;
    int warp = tid >> 5;
    int wm = (warp >> 2) * 64;
    int wn = (warp & 3) * 32;
    int g  = lane >> 2;
    int tg = lane & 3;
    int m0 = blockIdx.y * 128;
    int n0 = blockIdx.x * 128;

    int prow   = tid >> 2;
    int pchunk = (tid & 3) << 2;
    int psw    = ((prow >> 1) & 3) << 2;
    int dA = prow * 16 + (pchunk ^ psw);
    const float* Ag   = A  + (size_t)(m0 + prow) * lda + pchunk;
    const float* Ag64 = Ag + (size_t)64 * lda;
    const float* Bg   = Bw + (size_t)(n0 + prow) * ldb + pchunk;
    const float* Bg64 = Bg + (size_t)64 * ldb;

    auto prefetch = [&](int st, int k0) {
        float* sA = sm + st * STAGE_F;
        float* sB = sA + 2048;
        cpasync16(sA + dA,        Ag   + k0);
        cpasync16(sA + dA + 1024, Ag64 + k0);
        cpasync16(sB + dA,        Bg   + k0);
        cpasync16(sB + dA + 1024, Bg64 + k0);
        asm volatile("cp.async.commit_group;\n" ::);
    };

    float acc[4][4][4];
#pragma unroll
    for (int i = 0; i < 4; ++i)
#pragma unroll
        for (int j = 0; j < 4; ++j)
#pragma unroll
            for (int q = 0; q < 4; ++q) acc[i][j][q] = 0.f;

    int ktiles = K >> 4;
    prefetch(0, 0); prefetch(1, 16); prefetch(2, 32);
    int swz = ((g >> 1) & 3) << 2;

    for (int kt = 0; kt < ktiles; ++kt) {
        asm volatile("cp.async.wait_group 2;\n" ::);
        __syncthreads();
        if (kt + 3 < ktiles) prefetch((kt + 3) & 3, (kt + 3) << 4);
        else asm volatile("cp.async.commit_group;\n" ::);

        const unsigned* sA = (const unsigned*)(sm + (kt & 3) * STAGE_F);
        const unsigned* sB = sA + 2048;
        const unsigned* pA = sA + (wm + g) * 16;
        const unsigned* pB = sB + (wn + g) * 16;

#pragma unroll
        for (int ks = 0; ks < 2; ++ks) {
            int c0 = (ks * 8 + tg) ^ swz;
            int c4 = (ks * 8 + tg + 4) ^ swz;
            unsigned af[4][4], bf[4][2];
#pragma unroll
            for (int i = 0; i < 4; ++i) {
                af[i][0] = pA[i * 256 + c0];
                af[i][1] = pA[i * 256 + 128 + c0];
                af[i][2] = pA[i * 256 + c4];
                af[i][3] = pA[i * 256 + 128 + c4];
            }
#pragma unroll
            for (int j = 0; j < 4; ++j) {
                bf[j][0] = pB[j * 128 + c0];
                bf[j][1] = pB[j * 128 + c4];
            }
#pragma unroll
            for (int i = 0; i < 4; ++i)
#pragma unroll
                for (int j = 0; j < 4; ++j)
                    mma_tf32(acc[i][j], af[i], bf[j]);
        }
    }

#pragma unroll
    for (int i = 0; i < 4; ++i) {
        int r0 = m0 + wm + i * 16 + g;
#pragma unroll
        for (int j = 0; j < 4; ++j) {
            int c = n0 + wn + j * 8 + 2 * tg;
            float v0 = acc[i][j][0], v1 = acc[i][j][1];
            float v2 = acc[i][j][2], v3 = acc[i][j][3];
            if (Cinit) {
                float2 p0 = *(const float2*)&Cinit[(size_t)r0 * ldc + c];
                float2 p1 = *(const float2*)&Cinit[(size_t)(r0 + 8) * ldc + c];
                v0 += p0.x; v1 += p0.y; v2 += p1.x; v3 += p1.y;
            }
            if (bias) {
                float2 bb = *(const float2*)&bias[c];
                v0 += bb.x; v1 += bb.y; v2 += bb.x; v3 += bb.y;
            }
            if (round_out) {
                v0 = f2tff(v0); v1 = f2tff(v1); v2 = f2tff(v2); v3 = f2tff(v3);
            }
            *(float2*)&C[(size_t)r0 * ldc + c]       = make_float2(v0, v1);
            *(float2*)&C[(size_t)(r0 + 8) * ldc + c] = make_float2(v2, v3);
        }
    }
}

// ---------------------------------------------------------------------------
// MHA core per (l, b, h): lane-parallel scores, smem-broadcast PV.
// ---------------------------------------------------------------------------
#define APAD 68   // row stride (floats): 272B; conflict-free for LDS.32/.128

__global__ __launch_bounds__(768)
void attn_kernel(const float* __restrict__ qkv, const float* __restrict__ mask,
                 float* __restrict__ att) {
    cudaGridDependencySynchronize();
    int bid = blockIdx.x;
    int h = bid & 1;
    int b = (bid >> 1) & 63;
    int l = bid >> 7;

    __shared__ __align__(16) float qs[RR * APAD];
    __shared__ __align__(16) float ks[32 * APAD];   // rows 24..31 zeroed
    __shared__ __align__(16) float vs[RR * APAD];
    __shared__ float ps[RR * 32];

    int tid = threadIdx.x;
    for (int idx = tid; idx < RR * 64; idx += 768) {
        int s = idx >> 6, d = idx & 63;
        int base = ((l * RR + s) * BB + b) * 384 + h * 64 + d;
        qs[s * APAD + d] = qkv[base];
        ks[s * APAD + d] = qkv[base + 128];
        vs[s * APAD + d] = qkv[base + 256];
    }
    for (int idx = tid; idx < 8 * 64; idx += 768) {   // zero pad rows of ks
        int s = RR + (idx >> 6), d = idx & 63;
        ks[s * APAD + d] = 0.f;
    }
    __syncthreads();

    int w = tid >> 5, lane = tid & 31;
    if (w >= RR) return;
    int r = w;

    // scores: lane j computes q[r]·k[j]
    float4 a4 = make_float4(0.f, 0.f, 0.f, 0.f);
#pragma unroll
    for (int d4 = 0; d4 < 16; ++d4) {
        float4 qv = *(const float4*)&qs[r * APAD + 4 * d4];
        float4 kv = *(const float4*)&ks[lane * APAD + 4 * d4];
        a4.x = fmaf(qv.x, kv.x, a4.x);
        a4.y = fmaf(qv.y, kv.y, a4.y);
        a4.z = fmaf(qv.z, kv.z, a4.z);
        a4.w = fmaf(qv.w, kv.w, a4.w);
    }
    float sc = (a4.x + a4.y) + (a4.z + a4.w);
    float sco = (lane < RR) ? sc * 0.125f + mask[r * RR + lane] : -INFINITY;

    float mx = sco;
#pragma unroll
    for (int off = 16; off; off >>= 1)
        mx = fmaxf(mx, __shfl_xor_sync(0xffffffffu, mx, off));
    float e = __expf(sco - mx);                 // lanes >= 24 -> 0
    float sum = e;
#pragma unroll
    for (int off = 16; off; off >>= 1)
        sum += __shfl_xor_sync(0xffffffffu, sum, off);
    ps[r * 32 + lane] = e / sum;
    __syncwarp();

    // PV: lane handles dims (lane, lane+32)
    float acc0 = 0.f, acc1 = 0.f;
#pragma unroll
    for (int s = 0; s < RR; ++s) {
        float p = ps[r * 32 + s];
        acc0 = fmaf(p, vs[s * APAD + lane], acc0);
        acc1 = fmaf(p, vs[s * APAD + lane + 32], acc1);
    }
    int mo = ((l * RR + r) * BB + b) * EMB + h * 64;
    att[mo + lane]      = f2tff(acc0);
    att[mo + 32 + lane] = f2tff(acc1);
}

// ---------------------------------------------------------------------------
// Gate / state update / outputs. g2 (optional) = second split-K partial.
// ---------------------------------------------------------------------------
__global__ __launch_bounds__(256)
void gate_kernel(const float* __restrict__ g,
                 const float* __restrict__ g2,
                 const float* __restrict__ hin,
                 float* __restrict__ hout,
                 const float* __restrict__ Bias,
                 float* __restrict__ out_all,
                 float* __restrict__ out_col,
                 float* __restrict__ out_row,
                 int s) {
    cudaGridDependencySynchronize();
    int idx = blockIdx.x * 256 + threadIdx.x;   // M1*HH/4 = 98304
    int c = idx & 63;
    int m = idx >> 6;
    int b = m & 63;
    int r = m >> 6;

    const float4* G = (const float4*)(g + (size_t)m * 1536);
    float4 q[6];
#pragma unroll
    for (int t = 0; t < 6; ++t) q[t] = G[c + t * 64];
    if (g2) {
        const float4* G2 = (const float4*)(g2 + (size_t)m * 1536);
#pragma unroll
        for (int t = 0; t < 6; ++t) {
            float4 p = G2[c + t * 64];
            q[t].x += p.x; q[t].y += p.y; q[t].z += p.z; q[t].w += p.w;
        }
    }
    if (r <= s && s < RR) {
        const float4* B4 = (const float4*)Bias;
#pragma unroll
        for (int t = 0; t < 6; ++t) {
            float4 bb = B4[c + t * 64];
            q[t].x += bb.x; q[t].y += bb.y; q[t].z += bb.z; q[t].w += bb.w;
        }
    }
    float* qa = (float*)q;
    float4 hro = ((const float4*)(hin + (size_t)m * 512))[c];
    float4 hco = ((const float4*)(hin + (size_t)m * 512 + 256))[c];
    float* hrp = (float*)&hro;
    float* hcp = (float*)&hco;
    float hr[4], hc[4];
#pragma unroll
    for (int t = 0; t < 4; ++t) {
        float ug_r = sigf(qa[t]);
        float og_r = sigf(qa[4 + t]);
        float ug_c = sigf(qa[8 + t]);
        float og_c = sigf(qa[12 + t]);
        float ig_r = tanha(qa[16 + t]);
        float ig_c = tanha(qa[20 + t]);
        hr[t] = tanha((1.f - ug_r) * hrp[t] + ug_r * ig_r) * og_r;
        hc[t] = tanha((1.f - ug_c) * hcp[t] + ug_c * ig_c) * og_c;
    }
    float4 hr4 = make_float4(hr[0], hr[1], hr[2], hr[3]);
    float4 hc4 = make_float4(hc[0], hc[1], hc[2], hc[3]);

    int r2 = (r + 1) % RR;
    int mc = r2 * BB + b;
    ((float4*)(hout + (size_t)m * 512))[c]        = tf4(hr4);
    ((float4*)(hout + (size_t)mc * 512 + 256))[c] = tf4(hc4);

    float* ob = out_all + ((size_t)m * LSTEPS + s) * 512;
    __stcs((float4*)ob + c, hr4);
    __stcs((float4*)(ob + 256) + c, hc4);

    if (s >= OO - 1) {
        int t2 = s - (OO - 1);
        if (r == t2)      ((float4*)(out_row + (size_t)(b * RR + t2) * HH))[c] = hr4;
        if (r == RR - 1)  ((float4*)(out_col + (size_t)(b * OO + t2) * HH))[c] = hc4;
    }
}

// ---------------------------------------------------------------------------
// Launch
// ---------------------------------------------------------------------------
extern "C" void kernel_launch(void* const* d_in, const int* in_sizes, int n_in,
                              void* d_out, int out_size) {
    const float* input = (const float*)d_in[0];
    const float* mask  = (const float*)d_in[1];
    const float* W     = (const float*)d_in[2];
    const float* Bias  = (const float*)d_in[3];
    const float* inw   = (const float*)d_in[4];
    const float* inb   = (const float*)d_in[5];
    const float* outw  = (const float*)d_in[6];
    const float* outb  = (const float*)d_in[7];
    float* out = (float*)d_out;

    float *xy, *qkv, *att, *pre, *ht, *g, *Wt, *inwt, *outwt;
    cudaGetSymbolAddress((void**)&xy,    d_xy);
    cudaGetSymbolAddress((void**)&qkv,   d_qkv);
    cudaGetSymbolAddress((void**)&att,   d_att);
    cudaGetSymbolAddress((void**)&pre,   d_pre);
    cudaGetSymbolAddress((void**)&ht,    d_ht);
    cudaGetSymbolAddress((void**)&g,     d_g);
    cudaGetSymbolAddress((void**)&Wt,    d_Wt);
    cudaGetSymbolAddress((void**)&inwt,  d_inwt);
    cudaGetSymbolAddress((void**)&outwt, d_outwt);

    cudaFuncSetAttribute(gemm_mma, cudaFuncAttributeMaxDynamicSharedMemorySize, 65536);
    const int SMEMB = 65536;

    // 0) one-time tf32 rounding of weights (fused single launch)
    cvt_all_kernel<<<(W4 + IW4 + OW4 + 255) / 256, 256>>>(W, Wt, inw, inwt, outw, outwt);

    // 1) x (tf32)
    build_x_kernel<<<(MALL * 32 + 255) / 256, 256>>>(input, xy);

    // 2) qkv = x @ in_proj_wᵀ + b
    gemm_mma<<<dim3(3, MALL / 128), 256, SMEMB>>>(xy, 256, inwt, EMB, inb, nullptr,
                                                  qkv, 384, EMB, 0, 0);

    // 3) attention
    attn_kernel<<<LSTEPS * BB * 2, 768>>>(qkv, mask, att);

    // 4) y = att @ out_proj_wᵀ + b -> xy[:,128:256] (tf32)
    gemm_mma<<<dim3(1, MALL / 128), 256, SMEMB>>>(att, EMB, outwt, EMB, outb, nullptr,
                                                  xy + 128, 256, EMB, 1, 0);

    // 5) pre = [x|y] @ W[:, 512:768]ᵀ
    gemm_mma<<<dim3(12, MALL / 128), 256, SMEMB>>>(xy, 256, Wt + 512, 768, nullptr,
                                                   nullptr, pre, 1536, 256, 0, 0);

    // 6) zero initial state (buffer 0)
    cudaMemsetAsync(ht, 0, (size_t)M1 * 512 * sizeof(float));

    // PDL launch configs for the scan loop
    cudaLaunchAttribute pdlAttr[1];
    pdlAttr[0].id = cudaLaunchAttributeProgrammaticStreamSerialization;
    pdlAttr[0].val.programmaticStreamSerializationAllowed = 1;

    cudaLaunchConfig_t cfgGemm = {};
    cfgGemm.gridDim  = dim3(12, 12, 2);      // split-K = 2
    cfgGemm.blockDim = dim3(256);
    cfgGemm.dynamicSmemBytes = SMEMB;
    cfgGemm.stream = 0;
    cfgGemm.attrs = pdlAttr;
    cfgGemm.numAttrs = 1;

    cudaLaunchConfig_t cfgGate = {};
    cfgGate.gridDim  = dim3(384);
    cfgGate.blockDim = dim3(256);
    cfgGate.dynamicSmemBytes = 0;
    cfgGate.stream = 0;
    cfgGate.attrs = pdlAttr;
    cfgGate.numAttrs = 1;

    float* out_col = out + OUT_ALL_ELEMS;
    float* out_row = out + OUT_ALL_ELEMS + HID_ELEMS;
    float* g1 = g + (size_t)M1 * 1536;

    // 7) sequential scan; s=0 skips the GEMM (h == 0 -> g == pre[0])
    gate_kernel<<<384, 256>>>(pre, (const float*)nullptr, ht,
                              ht + (size_t)M1 * 512, Bias,
                              out, out_col, out_row, 0);
    for (int s = 1; s < LSTEPS; ++s) {
        const float* hin = ht + (size_t)(s & 1) * M1 * 512;
        float* hout      = ht + (size_t)((s + 1) & 1) * M1 * 512;
        cudaLaunchKernelEx(&cfgGemm, gemm_mma,
                           (const float*)hin, 512, (const float*)Wt, 768,
                           (const float*)nullptr,
                           (const float*)(pre + (size_t)s * M1 * 1536),
                           g, 1536, 256, 0, 256);
        cudaLaunchKernelEx(&cfgGate, gate_kernel,
                           (const float*)g, (const float*)g1, (const float*)hin, hout,
                           Bias, out, out_col, out_row, s);
    }
}

// round 11
// speedup vs baseline: 1.7289x; 1.4233x over previous
#include <cuda_runtime.h>
#include <cuda_fp16.h>
#include <cmath>

// Problem constants
#define LSTEPS 47
#define RR 24
#define OO 24
#define BB 64
#define EMB 128
#define HH 256
#define M1 1536        // RR * BB
#define MALL 72192     // LSTEPS * M1

#define OUT_ALL_ELEMS 36962304   // M1 * LSTEPS * 512
#define HID_ELEMS 393216         // BB * 24 * HH

// Scratch
__device__ __half d_xy[(size_t)MALL * 256];   // [x | y] packed fp16
__device__ float  d_qkv[(size_t)MALL * 384];
__device__ __half d_att[(size_t)MALL * 128];
__device__ float  d_pre[(size_t)MALL * 1536];
__device__ __half d_ht[2 * M1 * 512];         // fp16 state ping-pong [h_row|h_col]
__device__ float  d_g[2 * (size_t)M1 * 1536]; // split-K partial sums
__device__ __half d_Wt[1536 * 768];           // fp16 W
__device__ __half d_inwt[384 * 128];
__device__ __half d_outwt[128 * 128];

__device__ __forceinline__ float tanha(float x) {
    float y; asm("tanh.approx.f32 %0, %1;" : "=f"(y) : "f"(x)); return y;
}
__device__ __forceinline__ float sigf(float x) { return 1.f / (1.f + __expf(-x)); }

// ---------------------------------------------------------------------------
// Fused one-time weight conversion (float -> half)
// ---------------------------------------------------------------------------
#define W4   294912
#define IW4  12288
#define OW4  4096
__global__ void cvt_all_kernel(const float* __restrict__ W, __half* __restrict__ Wt,
                               const float* __restrict__ inw, __half* __restrict__ inwt,
                               const float* __restrict__ outw, __half* __restrict__ outwt) {
    int i = blockIdx.x * 256 + threadIdx.x;
    const float4* src; __half2* dst; int j;
    if (i < W4) {
        src = (const float4*)W; dst = (__half2*)Wt; j = i;
    } else if (i < W4 + IW4) {
        src = (const float4*)inw; dst = (__half2*)inwt; j = i - W4;
    } else if (i < W4 + IW4 + OW4) {
        src = (const float4*)outw; dst = (__half2*)outwt; j = i - W4 - IW4;
    } else return;
    float4 v = src[j];
    dst[j * 2]     = __floats2half2_rn(v.x, v.y);
    dst[j * 2 + 1] = __floats2half2_rn(v.z, v.w);
}

// ---------------------------------------------------------------------------
// build x (fp16): xy[m*256 + i] = input[b, l-r, r, i] (zero outside)
// ---------------------------------------------------------------------------
__global__ void build_x_kernel(const float* __restrict__ input, __half* __restrict__ xy) {
    int idx = blockIdx.x * 256 + threadIdx.x;
    if (idx >= MALL * 32) return;
    int c = idx & 31;
    int m = idx >> 5;
    int b = m & 63;
    int t = m >> 6;
    int r = t % RR;
    int l = t / RR;
    int o = l - r;
    __half2 h0 = __floats2half2_rn(0.f, 0.f), h1 = h0;
    if (o >= 0 && o < OO) {
        float4 v = ((const float4*)(input + (size_t)((b * OO + o) * RR + r) * EMB))[c];
        h0 = __floats2half2_rn(v.x, v.y);
        h1 = __floats2half2_rn(v.z, v.w);
    }
    __half2* p = (__half2*)(xy + (size_t)m * 256) + c * 2;
    p[0] = h0; p[1] = h1;
}

// ---------------------------------------------------------------------------
// MMA / cp.async primitives
// ---------------------------------------------------------------------------
__device__ __forceinline__ void mma_f16(float* d, const unsigned* a, const unsigned* b) {
    asm volatile(
        "mma.sync.aligned.m16n8k16.row.col.f32.f16.f16.f32 "
        "{%0,%1,%2,%3}, {%4,%5,%6,%7}, {%8,%9}, {%0,%1,%2,%3};\n"
        : "+f"(d[0]), "+f"(d[1]), "+f"(d[2]), "+f"(d[3])
        : "r"(a[0]), "r"(a[1]), "r"(a[2]), "r"(a[3]), "r"(b[0]), "r"(b[1]));
}
__device__ __forceinline__ void cpasync16(void* dst, const void* src) {
    unsigned saddr = (unsigned)__cvta_generic_to_shared(dst);
    asm volatile("cp.async.cg.shared.global [%0], [%1], 16;\n" :: "r"(saddr), "l"(src));
}

// ===========================================================================
// FP16 MMA GEMM (128x128 tile, BK=32 halves, 4-stage cp.async).
// C = A @ Bwᵀ (+Cinit)(+bias). A,Bw fp16 row-major-k. C fp32, or fp16 if
// out_half. ksplit: grid.z slices K; slice z writes C + z*M1*ldc, Cinit z=0.
// K multiple of 32 (in halves). Smem layout identical (in 4B units) to the
// validated tf32 kernel: same swizzle, same fragment addressing.
// ===========================================================================
#define STAGE_U 4096   // uints per stage (A 2048 + B 2048) = 16KB

__global__ __launch_bounds__(256, 2)
void gemm_mma(const __half* __restrict__ A, int lda,
              const __half* __restrict__ Bw, int ldb,
              const float* __restrict__ bias,
              const float* __restrict__ Cinit,
              float* __restrict__ C, int ldc, int K, int out_half, int ksplit)
{
    cudaGridDependencySynchronize();   // no-op unless launched with PDL attr
    extern __shared__ unsigned sm[];
    int kh = blockIdx.z;
    if (kh) {
        A += kh * ksplit;
        Bw += kh * ksplit;
        C += (size_t)kh * M1 * ldc;
        Cinit = nullptr;
    }
    int tid  = threadIdx.x;
    int lane = tid & 31;
    int warp = tid >> 5;
    int wm = (warp >> 2) * 64;
    int wn = (warp & 3) * 32;
    int g  = lane >> 2;
    int tg = lane & 3;
    int m0 = blockIdx.y * 128;
    int n0 = blockIdx.x * 128;

    int prow = tid >> 2;                 // 0..63
    int pch  = (tid & 3) << 2;           // half2-chunk offset {0,4,8,12}
    int psw  = ((prow >> 1) & 3) << 2;
    int dA   = prow * 16 + (pch ^ psw);  // uint units
    const __half* Ag   = A  + (size_t)(m0 + prow) * lda + pch * 2;
    const __half* Ag64 = Ag + (size_t)64 * lda;
    const __half* Bg   = Bw + (size_t)(n0 + prow) * ldb + pch * 2;
    const __half* Bg64 = Bg + (size_t)64 * ldb;

    auto prefetch = [&](int st, int k0) {   // k0 in halves
        unsigned* sA = sm + st * STAGE_U;
        unsigned* sB = sA + 2048;
        cpasync16(sA + dA,        Ag   + k0);
        cpasync16(sA + dA + 1024, Ag64 + k0);
        cpasync16(sB + dA,        Bg   + k0);
        cpasync16(sB + dA + 1024, Bg64 + k0);
        asm volatile("cp.async.commit_group;\n" ::);
    };

    float acc[4][4][4];
#pragma unroll
    for (int i = 0; i < 4; ++i)
#pragma unroll
        for (int j = 0; j < 4; ++j)
#pragma unroll
            for (int q = 0; q < 4; ++q) acc[i][j][q] = 0.f;

    int ktiles = K >> 5;                 // 32 halves per tile
    prefetch(0, 0); prefetch(1, 32); prefetch(2, 64);
    int swz = ((g >> 1) & 3) << 2;

    for (int kt = 0; kt < ktiles; ++kt) {
        asm volatile("cp.async.wait_group 2;\n" ::);
        __syncthreads();
        if (kt + 3 < ktiles) prefetch((kt + 3) & 3, (kt + 3) << 5);
        else asm volatile("cp.async.commit_group;\n" ::);

        const unsigned* sA = sm + (kt & 3) * STAGE_U;
        const unsigned* sB = sA + 2048;
        const unsigned* pA = sA + (wm + g) * 16;
        const unsigned* pB = sB + (wn + g) * 16;

#pragma unroll
        for (int ks = 0; ks < 2; ++ks) {    // two k16 steps per tile
            int c0 = (ks * 8 + tg) ^ swz;
            int c4 = (ks * 8 + tg + 4) ^ swz;
            unsigned af[4][4], bf[4][2];
#pragma unroll
            for (int i = 0; i < 4; ++i) {
                af[i][0] = pA[i * 256 + c0];
                af[i][1] = pA[i * 256 + 128 + c0];
                af[i][2] = pA[i * 256 + c4];
                af[i][3] = pA[i * 256 + 128 + c4];
            }
#pragma unroll
            for (int j = 0; j < 4; ++j) {
                bf[j][0] = pB[j * 128 + c0];
                bf[j][1] = pB[j * 128 + c4];
            }
#pragma unroll
            for (int i = 0; i < 4; ++i)
#pragma unroll
                for (int j = 0; j < 4; ++j)
                    mma_f16(acc[i][j], af[i], bf[j]);
        }
    }

#pragma unroll
    for (int i = 0; i < 4; ++i) {
        int r0 = m0 + wm + i * 16 + g;
#pragma unroll
        for (int j = 0; j < 4; ++j) {
            int c = n0 + wn + j * 8 + 2 * tg;
            float v0 = acc[i][j][0], v1 = acc[i][j][1];
            float v2 = acc[i][j][2], v3 = acc[i][j][3];
            if (Cinit) {
                float2 p0 = *(const float2*)&Cinit[(size_t)r0 * ldc + c];
                float2 p1 = *(const float2*)&Cinit[(size_t)(r0 + 8) * ldc + c];
                v0 += p0.x; v1 += p0.y; v2 += p1.x; v3 += p1.y;
            }
            if (bias) {
                float2 bb = *(const float2*)&bias[c];
                v0 += bb.x; v1 += bb.y; v2 += bb.x; v3 += bb.y;
            }
            if (out_half) {
                __half* Ch = (__half*)C;
                *(__half2*)&Ch[(size_t)r0 * ldc + c]       = __floats2half2_rn(v0, v1);
                *(__half2*)&Ch[(size_t)(r0 + 8) * ldc + c] = __floats2half2_rn(v2, v3);
            } else {
                *(float2*)&C[(size_t)r0 * ldc + c]       = make_float2(v0, v1);
                *(float2*)&C[(size_t)(r0 + 8) * ldc + c] = make_float2(v2, v3);
            }
        }
    }
}

// ---------------------------------------------------------------------------
// MHA core per (l, b, h): lane-parallel scores, smem-broadcast PV.
// Reads fp32 qkv, writes fp16 att.
// ---------------------------------------------------------------------------
#define APAD 68

__global__ __launch_bounds__(768)
void attn_kernel(const float* __restrict__ qkv, const float* __restrict__ mask,
                 __half* __restrict__ att) {
    cudaGridDependencySynchronize();
    int bid = blockIdx.x;
    int h = bid & 1;
    int b = (bid >> 1) & 63;
    int l = bid >> 7;

    __shared__ __align__(16) float qs[RR * APAD];
    __shared__ __align__(16) float ks[32 * APAD];
    __shared__ __align__(16) float vs[RR * APAD];
    __shared__ float ps[RR * 32];

    int tid = threadIdx.x;
    for (int idx = tid; idx < RR * 64; idx += 768) {
        int s = idx >> 6, d = idx & 63;
        int base = ((l * RR + s) * BB + b) * 384 + h * 64 + d;
        qs[s * APAD + d] = qkv[base];
        ks[s * APAD + d] = qkv[base + 128];
        vs[s * APAD + d] = qkv[base + 256];
    }
    for (int idx = tid; idx < 8 * 64; idx += 768) {
        int s = RR + (idx >> 6), d = idx & 63;
        ks[s * APAD + d] = 0.f;
    }
    __syncthreads();

    int w = tid >> 5, lane = tid & 31;
    if (w >= RR) return;
    int r = w;

    float4 a4 = make_float4(0.f, 0.f, 0.f, 0.f);
#pragma unroll
    for (int d4 = 0; d4 < 16; ++d4) {
        float4 qv = *(const float4*)&qs[r * APAD + 4 * d4];
        float4 kv = *(const float4*)&ks[lane * APAD + 4 * d4];
        a4.x = fmaf(qv.x, kv.x, a4.x);
        a4.y = fmaf(qv.y, kv.y, a4.y);
        a4.z = fmaf(qv.z, kv.z, a4.z);
        a4.w = fmaf(qv.w, kv.w, a4.w);
    }
    float sc = (a4.x + a4.y) + (a4.z + a4.w);
    float sco = (lane < RR) ? sc * 0.125f + mask[r * RR + lane] : -INFINITY;

    float mx = sco;
#pragma unroll
    for (int off = 16; off; off >>= 1)
        mx = fmaxf(mx, __shfl_xor_sync(0xffffffffu, mx, off));
    float e = __expf(sco - mx);
    float sum = e;
#pragma unroll
    for (int off = 16; off; off >>= 1)
        sum += __shfl_xor_sync(0xffffffffu, sum, off);
    ps[r * 32 + lane] = e / sum;
    __syncwarp();

    float acc0 = 0.f, acc1 = 0.f;
#pragma unroll
    for (int s = 0; s < RR; ++s) {
        float p = ps[r * 32 + s];
        acc0 = fmaf(p, vs[s * APAD + lane], acc0);
        acc1 = fmaf(p, vs[s * APAD + lane + 32], acc1);
    }
    int mo = ((l * RR + r) * BB + b) * EMB + h * 64;
    att[mo + lane]      = __float2half_rn(acc0);
    att[mo + 32 + lane] = __float2half_rn(acc1);
}

// ---------------------------------------------------------------------------
// Gate / state update / outputs. fp16 state in/out; fp32 outputs.
// ---------------------------------------------------------------------------
__global__ __launch_bounds__(256)
void gate_kernel(const float* __restrict__ g,
                 const float* __restrict__ g2,
                 const __half* __restrict__ hin,
                 __half* __restrict__ hout,
                 const float* __restrict__ Bias,
                 float* __restrict__ out_all,
                 float* __restrict__ out_col,
                 float* __restrict__ out_row,
                 int s) {
    cudaGridDependencySynchronize();
    int idx = blockIdx.x * 256 + threadIdx.x;   // M1*HH/4 = 98304
    int c = idx & 63;
    int m = idx >> 6;
    int b = m & 63;
    int r = m >> 6;

    const float4* G = (const float4*)(g + (size_t)m * 1536);
    float4 q[6];
#pragma unroll
    for (int t = 0; t < 6; ++t) q[t] = G[c + t * 64];
    if (g2) {
        const float4* G2 = (const float4*)(g2 + (size_t)m * 1536);
#pragma unroll
        for (int t = 0; t < 6; ++t) {
            float4 p = G2[c + t * 64];
            q[t].x += p.x; q[t].y += p.y; q[t].z += p.z; q[t].w += p.w;
        }
    }
    if (r <= s && s < RR) {
        const float4* B4 = (const float4*)Bias;
#pragma unroll
        for (int t = 0; t < 6; ++t) {
            float4 bb = B4[c + t * 64];
            q[t].x += bb.x; q[t].y += bb.y; q[t].z += bb.z; q[t].w += bb.w;
        }
    }
    float* qa = (float*)q;

    const __half2* HR = (const __half2*)(hin + (size_t)m * 512) + c * 2;
    const __half2* HC = (const __half2*)(hin + (size_t)m * 512 + 256) + c * 2;
    float2 hr01 = __half22float2(HR[0]);
    float2 hr23 = __half22float2(HR[1]);
    float2 hc01 = __half22float2(HC[0]);
    float2 hc23 = __half22float2(HC[1]);
    float hrp[4] = {hr01.x, hr01.y, hr23.x, hr23.y};
    float hcp[4] = {hc01.x, hc01.y, hc23.x, hc23.y};

    float hr[4], hc[4];
#pragma unroll
    for (int t = 0; t < 4; ++t) {
        float ug_r = sigf(qa[t]);
        float og_r = sigf(qa[4 + t]);
        float ug_c = sigf(qa[8 + t]);
        float og_c = sigf(qa[12 + t]);
        float ig_r = tanha(qa[16 + t]);
        float ig_c = tanha(qa[20 + t]);
        hr[t] = tanha((1.f - ug_r) * hrp[t] + ug_r * ig_r) * og_r;
        hc[t] = tanha((1.f - ug_c) * hcp[t] + ug_c * ig_c) * og_c;
    }
    float4 hr4 = make_float4(hr[0], hr[1], hr[2], hr[3]);
    float4 hc4 = make_float4(hc[0], hc[1], hc[2], hc[3]);

    int r2 = (r + 1) % RR;
    int mc = r2 * BB + b;
    __half2* OR = (__half2*)(hout + (size_t)m * 512) + c * 2;
    __half2* OC = (__half2*)(hout + (size_t)mc * 512 + 256) + c * 2;
    OR[0] = __floats2half2_rn(hr[0], hr[1]);
    OR[1] = __floats2half2_rn(hr[2], hr[3]);
    OC[0] = __floats2half2_rn(hc[0], hc[1]);
    OC[1] = __floats2half2_rn(hc[2], hc[3]);

    float* ob = out_all + ((size_t)m * LSTEPS + s) * 512;
    __stcs((float4*)ob + c, hr4);
    __stcs((float4*)(ob + 256) + c, hc4);

    if (s >= OO - 1) {
        int t2 = s - (OO - 1);
        if (r == t2)      ((float4*)(out_row + (size_t)(b * RR + t2) * HH))[c] = hr4;
        if (r == RR - 1)  ((float4*)(out_col + (size_t)(b * OO + t2) * HH))[c] = hc4;
    }
}

// ---------------------------------------------------------------------------
// Launch
// ---------------------------------------------------------------------------
extern "C" void kernel_launch(void* const* d_in, const int* in_sizes, int n_in,
                              void* d_out, int out_size) {
    const float* input = (const float*)d_in[0];
    const float* mask  = (const float*)d_in[1];
    const float* W     = (const float*)d_in[2];
    const float* Bias  = (const float*)d_in[3];
    const float* inw   = (const float*)d_in[4];
    const float* inb   = (const float*)d_in[5];
    const float* outw  = (const float*)d_in[6];
    const float* outb  = (const float*)d_in[7];
    float* out = (float*)d_out;

    __half *xy, *att, *ht, *Wt, *inwt, *outwt;
    float *qkv, *pre, *g;
    cudaGetSymbolAddress((void**)&xy,    d_xy);
    cudaGetSymbolAddress((void**)&qkv,   d_qkv);
    cudaGetSymbolAddress((void**)&att,   d_att);
    cudaGetSymbolAddress((void**)&pre,   d_pre);
    cudaGetSymbolAddress((void**)&ht,    d_ht);
    cudaGetSymbolAddress((void**)&g,     d_g);
    cudaGetSymbolAddress((void**)&Wt,    d_Wt);
    cudaGetSymbolAddress((void**)&inwt,  d_inwt);
    cudaGetSymbolAddress((void**)&outwt, d_outwt);

    cudaFuncSetAttribute(gemm_mma, cudaFuncAttributeMaxDynamicSharedMemorySize, 65536);
    const int SMEMB = 65536;

    // 0) one-time weight conversion to fp16
    cvt_all_kernel<<<(W4 + IW4 + OW4 + 255) / 256, 256>>>(W, Wt, inw, inwt, outw, outwt);

    // 1) x (fp16)
    build_x_kernel<<<(MALL * 32 + 255) / 256, 256>>>(input, xy);

    // 2) qkv = x @ in_proj_wᵀ + b  (fp32 out)
    gemm_mma<<<dim3(3, MALL / 128), 256, SMEMB>>>(xy, 256, inwt, EMB, inb, nullptr,
                                                  qkv, 384, EMB, 0, 0);

    // 3) attention (fp16 att out)
    attn_kernel<<<LSTEPS * BB * 2, 768>>>(qkv, mask, att);

    // 4) y = att @ out_proj_wᵀ + b -> xy[:,128:256] (fp16 out)
    gemm_mma<<<dim3(1, MALL / 128), 256, SMEMB>>>(att, EMB, outwt, EMB, outb, nullptr,
                                                  (float*)(xy + 128), 256, EMB, 1, 0);

    // 5) pre = [x|y] @ W[:, 512:768]ᵀ (fp32 out)
    gemm_mma<<<dim3(12, MALL / 128), 256, SMEMB>>>(xy, 256, Wt + 512, 768, nullptr,
                                                   nullptr, pre, 1536, 256, 0, 0);

    // 6) zero initial state (buffer 0)
    cudaMemsetAsync(ht, 0, (size_t)M1 * 512 * sizeof(__half));

    // PDL launch configs for the scan loop
    cudaLaunchAttribute pdlAttr[1];
    pdlAttr[0].id = cudaLaunchAttributeProgrammaticStreamSerialization;
    pdlAttr[0].val.programmaticStreamSerializationAllowed = 1;

    cudaLaunchConfig_t cfgGemm = {};
    cfgGemm.gridDim  = dim3(12, 12, 2);      // split-K = 2
    cfgGemm.blockDim = dim3(256);
    cfgGemm.dynamicSmemBytes = SMEMB;
    cfgGemm.stream = 0;
    cfgGemm.attrs = pdlAttr;
    cfgGemm.numAttrs = 1;

    cudaLaunchConfig_t cfgGate = {};
    cfgGate.gridDim  = dim3(384);
    cfgGate.blockDim = dim3(256);
    cfgGate.dynamicSmemBytes = 0;
    cfgGate.stream = 0;
    cfgGate.attrs = pdlAttr;
    cfgGate.numAttrs = 1;

    float* out_col = out + OUT_ALL_ELEMS;
    float* out_row = out + OUT_ALL_ELEMS + HID_ELEMS;
    float* g1 = g + (size_t)M1 * 1536;

    // 7) sequential scan; s=0 skips the GEMM (h == 0 -> g == pre[0])
    gate_kernel<<<384, 256>>>(pre, (const float*)nullptr, ht,
                              ht + (size_t)M1 * 512, Bias,
                              out, out_col, out_row, 0);
    for (int s = 1; s < LSTEPS; ++s) {
        const __half* hin = ht + (size_t)(s & 1) * M1 * 512;
        __half* hout      = ht + (size_t)((s + 1) & 1) * M1 * 512;
        cudaLaunchKernelEx(&cfgGemm, gemm_mma,
                           hin, 512, (const __half*)Wt, 768,
                           (const float*)nullptr,
                           (const float*)(pre + (size_t)s * M1 * 1536),
                           g, 1536, 256, 0, 256);
        cudaLaunchKernelEx(&cfgGate, gate_kernel,
                           (const float*)g, (const float*)g1, hin, hout,
                           Bias, out, out_col, out_row, s);
    }
}

// round 12
// speedup vs baseline: 1.7764x; 1.0275x over previous
#include <cuda_runtime.h>
#include <cuda_fp16.h>
#include <cmath>

// Problem constants
#define LSTEPS 47
#define RR 24
#define OO 24
#define BB 64
#define EMB 128
#define HH 256
#define M1 1536        // RR * BB
#define MALL 72192     // LSTEPS * M1

#define OUT_ALL_ELEMS 36962304   // M1 * LSTEPS * 512
#define HID_ELEMS 393216         // BB * 24 * HH

// Scratch
__device__ __half d_xy[(size_t)MALL * 256];   // [x | y] packed fp16
__device__ __half d_qkv[(size_t)MALL * 384];  // fp16 qkv
__device__ __half d_att[(size_t)MALL * 128];
__device__ __half d_pre[(size_t)MALL * 1536]; // fp16 gate pre-activations
__device__ __half d_ht[2 * M1 * 512];         // fp16 state ping-pong [h_row|h_col]
__device__ float  d_g[2 * (size_t)M1 * 1536]; // split-K partial sums (fp32)
__device__ __half d_Wt[1536 * 768];
__device__ __half d_inwt[384 * 128];
__device__ __half d_outwt[128 * 128];

__device__ __forceinline__ float tanha(float x) {
    float y; asm("tanh.approx.f32 %0, %1;" : "=f"(y) : "f"(x)); return y;
}
__device__ __forceinline__ float sigf(float x) { return 1.f / (1.f + __expf(-x)); }

// ---------------------------------------------------------------------------
// Fused one-time weight conversion (float -> half)
// ---------------------------------------------------------------------------
#define W4   294912
#define IW4  12288
#define OW4  4096
__global__ void cvt_all_kernel(const float* __restrict__ W, __half* __restrict__ Wt,
                               const float* __restrict__ inw, __half* __restrict__ inwt,
                               const float* __restrict__ outw, __half* __restrict__ outwt) {
    int i = blockIdx.x * 256 + threadIdx.x;
    const float4* src; __half2* dst; int j;
    if (i < W4) {
        src = (const float4*)W; dst = (__half2*)Wt; j = i;
    } else if (i < W4 + IW4) {
        src = (const float4*)inw; dst = (__half2*)inwt; j = i - W4;
    } else if (i < W4 + IW4 + OW4) {
        src = (const float4*)outw; dst = (__half2*)outwt; j = i - W4 - IW4;
    } else return;
    float4 v = src[j];
    dst[j * 2]     = __floats2half2_rn(v.x, v.y);
    dst[j * 2 + 1] = __floats2half2_rn(v.z, v.w);
}

// ---------------------------------------------------------------------------
// build x (fp16): xy[m*256 + i] = input[b, l-r, r, i] (zero outside)
// ---------------------------------------------------------------------------
__global__ void build_x_kernel(const float* __restrict__ input, __half* __restrict__ xy) {
    int idx = blockIdx.x * 256 + threadIdx.x;
    if (idx >= MALL * 32) return;
    int c = idx & 31;
    int m = idx >> 5;
    int b = m & 63;
    int t = m >> 6;
    int r = t % RR;
    int l = t / RR;
    int o = l - r;
    __half2 h0 = __floats2half2_rn(0.f, 0.f), h1 = h0;
    if (o >= 0 && o < OO) {
        float4 v = ((const float4*)(input + (size_t)((b * OO + o) * RR + r) * EMB))[c];
        h0 = __floats2half2_rn(v.x, v.y);
        h1 = __floats2half2_rn(v.z, v.w);
    }
    __half2* p = (__half2*)(xy + (size_t)m * 256) + c * 2;
    p[0] = h0; p[1] = h1;
}

// ---------------------------------------------------------------------------
// MMA / cp.async primitives
// ---------------------------------------------------------------------------
__device__ __forceinline__ void mma_f16(float* d, const unsigned* a, const unsigned* b) {
    asm volatile(
        "mma.sync.aligned.m16n8k16.row.col.f32.f16.f16.f32 "
        "{%0,%1,%2,%3}, {%4,%5,%6,%7}, {%8,%9}, {%0,%1,%2,%3};\n"
        : "+f"(d[0]), "+f"(d[1]), "+f"(d[2]), "+f"(d[3])
        : "r"(a[0]), "r"(a[1]), "r"(a[2]), "r"(a[3]), "r"(b[0]), "r"(b[1]));
}
__device__ __forceinline__ void cpasync16(void* dst, const void* src) {
    unsigned saddr = (unsigned)__cvta_generic_to_shared(dst);
    asm volatile("cp.async.cg.shared.global [%0], [%1], 16;\n" :: "r"(saddr), "l"(src));
}

// ===========================================================================
// FP16 MMA GEMM (128x128 tile, BK=32 halves, 4-stage cp.async).
// C = A @ Bwᵀ (+Cinit fp32|fp16)(+bias). out_half selects fp16 C.
// ksplit: grid.z slices K; slice z writes C + z*M1*ldc, Cinit only z=0.
// ===========================================================================
#define STAGE_U 4096   // uints per stage (A 2048 + B 2048) = 16KB

__global__ __launch_bounds__(256, 2)
void gemm_mma(const __half* __restrict__ A, int lda,
              const __half* __restrict__ Bw, int ldb,
              const float* __restrict__ bias,
              const void* __restrict__ Cinit, int cinit_half,
              float* __restrict__ C, int ldc, int K, int out_half, int ksplit)
{
    cudaGridDependencySynchronize();
    extern __shared__ unsigned sm[];
    int kh = blockIdx.z;
    if (kh) {
        A += kh * ksplit;
        Bw += kh * ksplit;
        C += (size_t)kh * M1 * ldc;
        Cinit = nullptr;
    }
    int tid  = threadIdx.x;
    int lane = tid & 31;
    int warp = tid >> 5;
    int wm = (warp >> 2) * 64;
    int wn = (warp & 3) * 32;
    int g  = lane >> 2;
    int tg = lane & 3;
    int m0 = blockIdx.y * 128;
    int n0 = blockIdx.x * 128;

    int prow = tid >> 2;
    int pch  = (tid & 3) << 2;
    int psw  = ((prow >> 1) & 3) << 2;
    int dA   = prow * 16 + (pch ^ psw);
    const __half* Ag   = A  + (size_t)(m0 + prow) * lda + pch * 2;
    const __half* Ag64 = Ag + (size_t)64 * lda;
    const __half* Bg   = Bw + (size_t)(n0 + prow) * ldb + pch * 2;
    const __half* Bg64 = Bg + (size_t)64 * ldb;

    auto prefetch = [&](int st, int k0) {
        unsigned* sA = sm + st * STAGE_U;
        unsigned* sB = sA + 2048;
        cpasync16(sA + dA,        Ag   + k0);
        cpasync16(sA + dA + 1024, Ag64 + k0);
        cpasync16(sB + dA,        Bg   + k0);
        cpasync16(sB + dA + 1024, Bg64 + k0);
        asm volatile("cp.async.commit_group;\n" ::);
    };

    float acc[4][4][4];
#pragma unroll
    for (int i = 0; i < 4; ++i)
#pragma unroll
        for (int j = 0; j < 4; ++j)
#pragma unroll
            for (int q = 0; q < 4; ++q) acc[i][j][q] = 0.f;

    int ktiles = K >> 5;
    prefetch(0, 0); prefetch(1, 32); prefetch(2, 64);
    int swz = ((g >> 1) & 3) << 2;

    for (int kt = 0; kt < ktiles; ++kt) {
        asm volatile("cp.async.wait_group 2;\n" ::);
        __syncthreads();
        if (kt + 3 < ktiles) prefetch((kt + 3) & 3, (kt + 3) << 5);
        else asm volatile("cp.async.commit_group;\n" ::);

        const unsigned* sA = sm + (kt & 3) * STAGE_U;
        const unsigned* sB = sA + 2048;
        const unsigned* pA = sA + (wm + g) * 16;
        const unsigned* pB = sB + (wn + g) * 16;

#pragma unroll
        for (int ks = 0; ks < 2; ++ks) {
            int c0 = (ks * 8 + tg) ^ swz;
            int c4 = (ks * 8 + tg + 4) ^ swz;
            unsigned af[4][4], bf[4][2];
#pragma unroll
            for (int i = 0; i < 4; ++i) {
                af[i][0] = pA[i * 256 + c0];
                af[i][1] = pA[i * 256 + 128 + c0];
                af[i][2] = pA[i * 256 + c4];
                af[i][3] = pA[i * 256 + 128 + c4];
            }
#pragma unroll
            for (int j = 0; j < 4; ++j) {
                bf[j][0] = pB[j * 128 + c0];
                bf[j][1] = pB[j * 128 + c4];
            }
#pragma unroll
            for (int i = 0; i < 4; ++i)
#pragma unroll
                for (int j = 0; j < 4; ++j)
                    mma_f16(acc[i][j], af[i], bf[j]);
        }
    }

#pragma unroll
    for (int i = 0; i < 4; ++i) {
        int r0 = m0 + wm + i * 16 + g;
#pragma unroll
        for (int j = 0; j < 4; ++j) {
            int c = n0 + wn + j * 8 + 2 * tg;
            float v0 = acc[i][j][0], v1 = acc[i][j][1];
            float v2 = acc[i][j][2], v3 = acc[i][j][3];
            if (Cinit) {
                if (cinit_half) {
                    const __half* Ch = (const __half*)Cinit;
                    float2 p0 = __half22float2(*(const __half2*)&Ch[(size_t)r0 * ldc + c]);
                    float2 p1 = __half22float2(*(const __half2*)&Ch[(size_t)(r0 + 8) * ldc + c]);
                    v0 += p0.x; v1 += p0.y; v2 += p1.x; v3 += p1.y;
                } else {
                    const float* Cf = (const float*)Cinit;
                    float2 p0 = *(const float2*)&Cf[(size_t)r0 * ldc + c];
                    float2 p1 = *(const float2*)&Cf[(size_t)(r0 + 8) * ldc + c];
                    v0 += p0.x; v1 += p0.y; v2 += p1.x; v3 += p1.y;
                }
            }
            if (bias) {
                float2 bb = *(const float2*)&bias[c];
                v0 += bb.x; v1 += bb.y; v2 += bb.x; v3 += bb.y;
            }
            if (out_half) {
                __half* Ch = (__half*)C;
                *(__half2*)&Ch[(size_t)r0 * ldc + c]       = __floats2half2_rn(v0, v1);
                *(__half2*)&Ch[(size_t)(r0 + 8) * ldc + c] = __floats2half2_rn(v2, v3);
            } else {
                *(float2*)&C[(size_t)r0 * ldc + c]       = make_float2(v0, v1);
                *(float2*)&C[(size_t)(r0 + 8) * ldc + c] = make_float2(v2, v3);
            }
        }
    }
}

// ---------------------------------------------------------------------------
// MHA core per (l, b): both heads in one block. fp16 qkv in, fp16 att out.
// fp32 smem rows padded to 132 floats (132 % 32 == 4 -> LDS.128 conflict-free).
// ---------------------------------------------------------------------------
#define AP2 132

__global__ __launch_bounds__(768)
void attn_kernel(const __half* __restrict__ qkv, const float* __restrict__ mask,
                 __half* __restrict__ att) {
    cudaGridDependencySynchronize();
    int bid = blockIdx.x;
    int b = bid & 63;
    int l = bid >> 6;

    __shared__ __align__(16) float qs[RR * AP2];
    __shared__ __align__(16) float ks[32 * AP2];   // rows 24..31 zeroed
    __shared__ __align__(16) float vs[RR * AP2];
    __shared__ float ps[RR * 32];

    int tid = threadIdx.x;
    // load 24 rows x 192 half2 (q|k|v interleaved per row), coalesced
    for (int idx = tid; idx < RR * 192; idx += 768) {
        int s = idx / 192;
        int u = idx % 192;
        const __half2* row = (const __half2*)(qkv + ((size_t)(l * RR + s) * BB + b) * 384);
        float2 v = __half22float2(row[u]);
        int seg = u >> 6;          // 0=q, 1=k, 2=v
        int w2 = (u & 63) * 2;     // dim pair
        float* dst = (seg == 0) ? &qs[s * AP2 + w2]
                   : (seg == 1) ? &ks[s * AP2 + w2]
                                : &vs[s * AP2 + w2];
        *(float2*)dst = v;
    }
    for (int idx = tid; idx < 8 * 128; idx += 768) {   // zero ks pad rows
        int s = RR + (idx >> 7), d = idx & 127;
        ks[s * AP2 + d] = 0.f;
    }
    __syncthreads();

    int w = tid >> 5, lane = tid & 31;
    if (w >= RR) return;
    int r = w;
    float mk = (lane < RR) ? mask[r * RR + lane] : 0.f;

#pragma unroll
    for (int h = 0; h < 2; ++h) {
        int hb = h * 64;
        // scores: lane j computes q[r]·k[j] over 64 dims
        float4 a4 = make_float4(0.f, 0.f, 0.f, 0.f);
#pragma unroll
        for (int d4 = 0; d4 < 16; ++d4) {
            float4 qv = *(const float4*)&qs[r * AP2 + hb + 4 * d4];
            float4 kv = *(const float4*)&ks[lane * AP2 + hb + 4 * d4];
            a4.x = fmaf(qv.x, kv.x, a4.x);
            a4.y = fmaf(qv.y, kv.y, a4.y);
            a4.z = fmaf(qv.z, kv.z, a4.z);
            a4.w = fmaf(qv.w, kv.w, a4.w);
        }
        float sc = (a4.x + a4.y) + (a4.z + a4.w);
        float sco = (lane < RR) ? sc * 0.125f + mk : -INFINITY;

        float mx = sco;
#pragma unroll
        for (int off = 16; off; off >>= 1)
            mx = fmaxf(mx, __shfl_xor_sync(0xffffffffu, mx, off));
        float e = __expf(sco - mx);
        float sum = e;
#pragma unroll
        for (int off = 16; off; off >>= 1)
            sum += __shfl_xor_sync(0xffffffffu, sum, off);
        ps[r * 32 + lane] = e / sum;
        __syncwarp();

        float acc0 = 0.f, acc1 = 0.f;
#pragma unroll
        for (int s = 0; s < RR; ++s) {
            float p = ps[r * 32 + s];
            acc0 = fmaf(p, vs[s * AP2 + hb + lane], acc0);
            acc1 = fmaf(p, vs[s * AP2 + hb + lane + 32], acc1);
        }
        int mo = ((l * RR + r) * BB + b) * EMB + hb;
        att[mo + lane]      = __float2half_rn(acc0);
        att[mo + 32 + lane] = __float2half_rn(acc1);
        __syncwarp();
    }
}

// ---------------------------------------------------------------------------
// Gate / state update / outputs. g: fp32 (or fp16 when g_half, used at s=0).
// ---------------------------------------------------------------------------
__global__ __launch_bounds__(256)
void gate_kernel(const void* __restrict__ g, int g_half,
                 const float* __restrict__ g2,
                 const __half* __restrict__ hin,
                 __half* __restrict__ hout,
                 const float* __restrict__ Bias,
                 float* __restrict__ out_all,
                 float* __restrict__ out_col,
                 float* __restrict__ out_row,
                 int s) {
    cudaGridDependencySynchronize();
    int idx = blockIdx.x * 256 + threadIdx.x;   // M1*HH/4 = 98304
    int c = idx & 63;
    int m = idx >> 6;
    int b = m & 63;
    int r = m >> 6;

    float4 q[6];
    if (g_half) {
        const __half2* Gh = (const __half2*)g + (size_t)m * 768;
#pragma unroll
        for (int t = 0; t < 6; ++t) {
            float2 a = __half22float2(Gh[(c + t * 64) * 2]);
            float2 bb = __half22float2(Gh[(c + t * 64) * 2 + 1]);
            q[t] = make_float4(a.x, a.y, bb.x, bb.y);
        }
    } else {
        const float4* G = (const float4*)g + (size_t)m * 384;
#pragma unroll
        for (int t = 0; t < 6; ++t) q[t] = G[c + t * 64];
    }
    if (g2) {
        const float4* G2 = (const float4*)(g2 + (size_t)m * 1536);
#pragma unroll
        for (int t = 0; t < 6; ++t) {
            float4 p = G2[c + t * 64];
            q[t].x += p.x; q[t].y += p.y; q[t].z += p.z; q[t].w += p.w;
        }
    }
    if (r <= s && s < RR) {
        const float4* B4 = (const float4*)Bias;
#pragma unroll
        for (int t = 0; t < 6; ++t) {
            float4 bb = B4[c + t * 64];
            q[t].x += bb.x; q[t].y += bb.y; q[t].z += bb.z; q[t].w += bb.w;
        }
    }
    float* qa = (float*)q;

    const __half2* HR = (const __half2*)(hin + (size_t)m * 512) + c * 2;
    const __half2* HC = (const __half2*)(hin + (size_t)m * 512 + 256) + c * 2;
    float2 hr01 = __half22float2(HR[0]);
    float2 hr23 = __half22float2(HR[1]);
    float2 hc01 = __half22float2(HC[0]);
    float2 hc23 = __half22float2(HC[1]);
    float hrp[4] = {hr01.x, hr01.y, hr23.x, hr23.y};
    float hcp[4] = {hc01.x, hc01.y, hc23.x, hc23.y};

    float hr[4], hc[4];
#pragma unroll
    for (int t = 0; t < 4; ++t) {
        float ug_r = sigf(qa[t]);
        float og_r = sigf(qa[4 + t]);
        float ug_c = sigf(qa[8 + t]);
        float og_c = sigf(qa[12 + t]);
        float ig_r = tanha(qa[16 + t]);
        float ig_c = tanha(qa[20 + t]);
        hr[t] = tanha((1.f - ug_r) * hrp[t] + ug_r * ig_r) * og_r;
        hc[t] = tanha((1.f - ug_c) * hcp[t] + ug_c * ig_c) * og_c;
    }
    float4 hr4 = make_float4(hr[0], hr[1], hr[2], hr[3]);
    float4 hc4 = make_float4(hc[0], hc[1], hc[2], hc[3]);

    int r2 = (r + 1) % RR;
    int mc = r2 * BB + b;
    __half2* OR = (__half2*)(hout + (size_t)m * 512) + c * 2;
    __half2* OC = (__half2*)(hout + (size_t)mc * 512 + 256) + c * 2;
    OR[0] = __floats2half2_rn(hr[0], hr[1]);
    OR[1] = __floats2half2_rn(hr[2], hr[3]);
    OC[0] = __floats2half2_rn(hc[0], hc[1]);
    OC[1] = __floats2half2_rn(hc[2], hc[3]);

    float* ob = out_all + ((size_t)m * LSTEPS + s) * 512;
    __stcs((float4*)ob + c, hr4);
    __stcs((float4*)(ob + 256) + c, hc4);

    if (s >= OO - 1) {
        int t2 = s - (OO - 1);
        if (r == t2)      ((float4*)(out_row + (size_t)(b * RR + t2) * HH))[c] = hr4;
        if (r == RR - 1)  ((float4*)(out_col + (size_t)(b * OO + t2) * HH))[c] = hc4;
    }
}

// ---------------------------------------------------------------------------
// Launch
// ---------------------------------------------------------------------------
extern "C" void kernel_launch(void* const* d_in, const int* in_sizes, int n_in,
                              void* d_out, int out_size) {
    const float* input = (const float*)d_in[0];
    const float* mask  = (const float*)d_in[1];
    const float* W     = (const float*)d_in[2];
    const float* Bias  = (const float*)d_in[3];
    const float* inw   = (const float*)d_in[4];
    const float* inb   = (const float*)d_in[5];
    const float* outw  = (const float*)d_in[6];
    const float* outb  = (const float*)d_in[7];
    float* out = (float*)d_out;

    __half *xy, *qkv, *att, *pre, *ht, *Wt, *inwt, *outwt;
    float *g;
    cudaGetSymbolAddress((void**)&xy,    d_xy);
    cudaGetSymbolAddress((void**)&qkv,   d_qkv);
    cudaGetSymbolAddress((void**)&att,   d_att);
    cudaGetSymbolAddress((void**)&pre,   d_pre);
    cudaGetSymbolAddress((void**)&ht,    d_ht);
    cudaGetSymbolAddress((void**)&g,     d_g);
    cudaGetSymbolAddress((void**)&Wt,    d_Wt);
    cudaGetSymbolAddress((void**)&inwt,  d_inwt);
    cudaGetSymbolAddress((void**)&outwt, d_outwt);

    cudaFuncSetAttribute(gemm_mma, cudaFuncAttributeMaxDynamicSharedMemorySize, 65536);
    const int SMEMB = 65536;

    // 0) one-time weight conversion to fp16
    cvt_all_kernel<<<(W4 + IW4 + OW4 + 255) / 256, 256>>>(W, Wt, inw, inwt, outw, outwt);

    // 1) x (fp16)
    build_x_kernel<<<(MALL * 32 + 255) / 256, 256>>>(input, xy);

    // 2) qkv = x @ in_proj_wᵀ + b  (fp16 out)
    gemm_mma<<<dim3(3, MALL / 128), 256, SMEMB>>>(xy, 256, inwt, EMB, inb,
                                                  nullptr, 0,
                                                  (float*)qkv, 384, EMB, 1, 0);

    // 3) attention (fp16 in/out, both heads per block)
    attn_kernel<<<LSTEPS * BB, 768>>>(qkv, mask, att);

    // 4) y = att @ out_proj_wᵀ + b -> xy[:,128:256] (fp16 out)
    gemm_mma<<<dim3(1, MALL / 128), 256, SMEMB>>>(att, EMB, outwt, EMB, outb,
                                                  nullptr, 0,
                                                  (float*)(xy + 128), 256, EMB, 1, 0);

    // 5) pre = [x|y] @ W[:, 512:768]ᵀ (fp16 out)
    gemm_mma<<<dim3(12, MALL / 128), 256, SMEMB>>>(xy, 256, Wt + 512, 768, nullptr,
                                                   nullptr, 0,
                                                   (float*)pre, 1536, 256, 1, 0);

    // 6) zero initial state (buffer 0)
    cudaMemsetAsync(ht, 0, (size_t)M1 * 512 * sizeof(__half));

    // PDL launch configs for the scan loop
    cudaLaunchAttribute pdlAttr[1];
    pdlAttr[0].id = cudaLaunchAttributeProgrammaticStreamSerialization;
    pdlAttr[0].val.programmaticStreamSerializationAllowed = 1;

    cudaLaunchConfig_t cfgGemm = {};
    cfgGemm.gridDim  = dim3(12, 12, 2);      // split-K = 2
    cfgGemm.blockDim = dim3(256);
    cfgGemm.dynamicSmemBytes = SMEMB;
    cfgGemm.stream = 0;
    cfgGemm.attrs = pdlAttr;
    cfgGemm.numAttrs = 1;

    cudaLaunchConfig_t cfgGate = {};
    cfgGate.gridDim  = dim3(384);
    cfgGate.blockDim = dim3(256);
    cfgGate.dynamicSmemBytes = 0;
    cfgGate.stream = 0;
    cfgGate.attrs = pdlAttr;
    cfgGate.numAttrs = 1;

    float* out_col = out + OUT_ALL_ELEMS;
    float* out_row = out + OUT_ALL_ELEMS + HID_ELEMS;
    float* g1 = g + (size_t)M1 * 1536;

    // 7) sequential scan; s=0 skips the GEMM (h == 0 -> g == pre[0], fp16)
    gate_kernel<<<384, 256>>>((const void*)pre, 1, (const float*)nullptr, ht,
                              ht + (size_t)M1 * 512, Bias,
                              out, out_col, out_row, 0);
    for (int s = 1; s < LSTEPS; ++s) {
        const __half* hin = ht + (size_t)(s & 1) * M1 * 512;
        __half* hout      = ht + (size_t)((s + 1) & 1) * M1 * 512;
        cudaLaunchKernelEx(&cfgGemm, gemm_mma,
                           hin, 512, (const __half*)Wt, 768,
                           (const float*)nullptr,
                           (const void*)(pre + (size_t)s * M1 * 1536), 1,
                           g, 1536, 256, 0, 256);
        cudaLaunchKernelEx(&cfgGate, gate_kernel,
                           (const void*)g, 0, (const float*)g1, hin, hout,
                           Bias, out, out_col, out_row, s);
    }
}

// round 13
// speedup vs baseline: 1.7783x; 1.0011x over previous
#include <cuda_runtime.h>
#include <cuda_fp16.h>
#include <cmath>

// Problem constants
#define LSTEPS 47
#define RR 24
#define OO 24
#define BB 64
#define EMB 128
#define HH 256
#define M1 1536        // RR * BB
#define MALL 72192     // LSTEPS * M1

#define OUT_ALL_ELEMS 36962304   // M1 * LSTEPS * 512
#define HID_ELEMS 393216         // BB * 24 * HH

// Scratch
__device__ __half d_xy[(size_t)MALL * 256];   // [x | y] packed fp16
__device__ __half d_qkv[(size_t)MALL * 384];  // fp16 qkv
__device__ __half d_att[(size_t)MALL * 128];
__device__ __half d_pre[(size_t)MALL * 1536]; // fp16 gate pre-activations
__device__ __half d_ht[2 * M1 * 512];         // fp16 state ping-pong [h_row|h_col]
__device__ __half d_g[2 * (size_t)M1 * 1536]; // fp16 split-K partial sums
__device__ __half d_Wt[1536 * 768];
__device__ __half d_inwt[384 * 128];
__device__ __half d_outwt[128 * 128];

__device__ __forceinline__ float tanha(float x) {
    float y; asm("tanh.approx.f32 %0, %1;" : "=f"(y) : "f"(x)); return y;
}
__device__ __forceinline__ float sigf(float x) { return 1.f / (1.f + __expf(-x)); }

// ---------------------------------------------------------------------------
// Fused one-time weight conversion (float -> half)
// ---------------------------------------------------------------------------
#define W4   294912
#define IW4  12288
#define OW4  4096
__global__ void cvt_all_kernel(const float* __restrict__ W, __half* __restrict__ Wt,
                               const float* __restrict__ inw, __half* __restrict__ inwt,
                               const float* __restrict__ outw, __half* __restrict__ outwt) {
    int i = blockIdx.x * 256 + threadIdx.x;
    const float4* src; __half2* dst; int j;
    if (i < W4) {
        src = (const float4*)W; dst = (__half2*)Wt; j = i;
    } else if (i < W4 + IW4) {
        src = (const float4*)inw; dst = (__half2*)inwt; j = i - W4;
    } else if (i < W4 + IW4 + OW4) {
        src = (const float4*)outw; dst = (__half2*)outwt; j = i - W4 - IW4;
    } else return;
    float4 v = src[j];
    dst[j * 2]     = __floats2half2_rn(v.x, v.y);
    dst[j * 2 + 1] = __floats2half2_rn(v.z, v.w);
}

// ---------------------------------------------------------------------------
// build x (fp16): xy[m*256 + i] = input[b, l-r, r, i] (zero outside)
// ---------------------------------------------------------------------------
__global__ void build_x_kernel(const float* __restrict__ input, __half* __restrict__ xy) {
    int idx = blockIdx.x * 256 + threadIdx.x;
    if (idx >= MALL * 32) return;
    int c = idx & 31;
    int m = idx >> 5;
    int b = m & 63;
    int t = m >> 6;
    int r = t % RR;
    int l = t / RR;
    int o = l - r;
    __half2 h0 = __floats2half2_rn(0.f, 0.f), h1 = h0;
    if (o >= 0 && o < OO) {
        float4 v = ((const float4*)(input + (size_t)((b * OO + o) * RR + r) * EMB))[c];
        h0 = __floats2half2_rn(v.x, v.y);
        h1 = __floats2half2_rn(v.z, v.w);
    }
    __half2* p = (__half2*)(xy + (size_t)m * 256) + c * 2;
    p[0] = h0; p[1] = h1;
}

// ---------------------------------------------------------------------------
// MMA / cp.async primitives
// ---------------------------------------------------------------------------
__device__ __forceinline__ void mma_f16(float* d, const unsigned* a, const unsigned* b) {
    asm volatile(
        "mma.sync.aligned.m16n8k16.row.col.f32.f16.f16.f32 "
        "{%0,%1,%2,%3}, {%4,%5,%6,%7}, {%8,%9}, {%0,%1,%2,%3};\n"
        : "+f"(d[0]), "+f"(d[1]), "+f"(d[2]), "+f"(d[3])
        : "r"(a[0]), "r"(a[1]), "r"(a[2]), "r"(a[3]), "r"(b[0]), "r"(b[1]));
}
__device__ __forceinline__ void cpasync16(void* dst, const void* src) {
    unsigned saddr = (unsigned)__cvta_generic_to_shared(dst);
    asm volatile("cp.async.cg.shared.global [%0], [%1], 16;\n" :: "r"(saddr), "l"(src));
}

// ===========================================================================
// FP16 MMA GEMM (128x128 tile, BK=32 halves, 4-stage cp.async).
// C = A @ Bwᵀ (+Cinit fp32|fp16)(+bias). out_half selects fp16 C.
// ksplit: grid.z slices K; slice z writes C + z*M1*ldc (element units of C's
// type), Cinit only z=0.
// ===========================================================================
#define STAGE_U 4096   // uints per stage (A 2048 + B 2048) = 16KB

__global__ __launch_bounds__(256, 2)
void gemm_mma(const __half* __restrict__ A, int lda,
              const __half* __restrict__ Bw, int ldb,
              const float* __restrict__ bias,
              const void* __restrict__ Cinit, int cinit_half,
              float* __restrict__ C, int ldc, int K, int out_half, int ksplit)
{
    cudaGridDependencySynchronize();
    extern __shared__ unsigned sm[];
    int kh = blockIdx.z;
    if (kh) {
        A += kh * ksplit;
        Bw += kh * ksplit;
        if (out_half) C = (float*)((__half*)C + (size_t)kh * M1 * ldc);
        else          C = C + (size_t)kh * M1 * ldc;
        Cinit = nullptr;
    }
    int tid  = threadIdx.x;
    int lane = tid & 31;
    int warp = tid >> 5;
    int wm = (warp >> 2) * 64;
    int wn = (warp & 3) * 32;
    int g  = lane >> 2;
    int tg = lane & 3;
    int m0 = blockIdx.y * 128;
    int n0 = blockIdx.x * 128;

    int prow = tid >> 2;
    int pch  = (tid & 3) << 2;
    int psw  = ((prow >> 1) & 3) << 2;
    int dA   = prow * 16 + (pch ^ psw);
    const __half* Ag   = A  + (size_t)(m0 + prow) * lda + pch * 2;
    const __half* Ag64 = Ag + (size_t)64 * lda;
    const __half* Bg   = Bw + (size_t)(n0 + prow) * ldb + pch * 2;
    const __half* Bg64 = Bg + (size_t)64 * ldb;

    auto prefetch = [&](int st, int k0) {
        unsigned* sA = sm + st * STAGE_U;
        unsigned* sB = sA + 2048;
        cpasync16(sA + dA,        Ag   + k0);
        cpasync16(sA + dA + 1024, Ag64 + k0);
        cpasync16(sB + dA,        Bg   + k0);
        cpasync16(sB + dA + 1024, Bg64 + k0);
        asm volatile("cp.async.commit_group;\n" ::);
    };

    float acc[4][4][4];
#pragma unroll
    for (int i = 0; i < 4; ++i)
#pragma unroll
        for (int j = 0; j < 4; ++j)
#pragma unroll
            for (int q = 0; q < 4; ++q) acc[i][j][q] = 0.f;

    int ktiles = K >> 5;
    prefetch(0, 0); prefetch(1, 32); prefetch(2, 64);
    int swz = ((g >> 1) & 3) << 2;

    for (int kt = 0; kt < ktiles; ++kt) {
        asm volatile("cp.async.wait_group 2;\n" ::);
        __syncthreads();
        if (kt + 3 < ktiles) prefetch((kt + 3) & 3, (kt + 3) << 5);
        else asm volatile("cp.async.commit_group;\n" ::);

        const unsigned* sA = sm + (kt & 3) * STAGE_U;
        const unsigned* sB = sA + 2048;
        const unsigned* pA = sA + (wm + g) * 16;
        const unsigned* pB = sB + (wn + g) * 16;

#pragma unroll
        for (int ks = 0; ks < 2; ++ks) {
            int c0 = (ks * 8 + tg) ^ swz;
            int c4 = (ks * 8 + tg + 4) ^ swz;
            unsigned af[4][4], bf[4][2];
#pragma unroll
            for (int i = 0; i < 4; ++i) {
                af[i][0] = pA[i * 256 + c0];
                af[i][1] = pA[i * 256 + 128 + c0];
                af[i][2] = pA[i * 256 + c4];
                af[i][3] = pA[i * 256 + 128 + c4];
            }
#pragma unroll
            for (int j = 0; j < 4; ++j) {
                bf[j][0] = pB[j * 128 + c0];
                bf[j][1] = pB[j * 128 + c4];
            }
#pragma unroll
            for (int i = 0; i < 4; ++i)
#pragma unroll
                for (int j = 0; j < 4; ++j)
                    mma_f16(acc[i][j], af[i], bf[j]);
        }
    }

#pragma unroll
    for (int i = 0; i < 4; ++i) {
        int r0 = m0 + wm + i * 16 + g;
#pragma unroll
        for (int j = 0; j < 4; ++j) {
            int c = n0 + wn + j * 8 + 2 * tg;
            float v0 = acc[i][j][0], v1 = acc[i][j][1];
            float v2 = acc[i][j][2], v3 = acc[i][j][3];
            if (Cinit) {
                if (cinit_half) {
                    const __half* Ch = (const __half*)Cinit;
                    float2 p0 = __half22float2(*(const __half2*)&Ch[(size_t)r0 * ldc + c]);
                    float2 p1 = __half22float2(*(const __half2*)&Ch[(size_t)(r0 + 8) * ldc + c]);
                    v0 += p0.x; v1 += p0.y; v2 += p1.x; v3 += p1.y;
                } else {
                    const float* Cf = (const float*)Cinit;
                    float2 p0 = *(const float2*)&Cf[(size_t)r0 * ldc + c];
                    float2 p1 = *(const float2*)&Cf[(size_t)(r0 + 8) * ldc + c];
                    v0 += p0.x; v1 += p0.y; v2 += p1.x; v3 += p1.y;
                }
            }
            if (bias) {
                float2 bb = *(const float2*)&bias[c];
                v0 += bb.x; v1 += bb.y; v2 += bb.x; v3 += bb.y;
            }
            if (out_half) {
                __half* Ch = (__half*)C;
                *(__half2*)&Ch[(size_t)r0 * ldc + c]       = __floats2half2_rn(v0, v1);
                *(__half2*)&Ch[(size_t)(r0 + 8) * ldc + c] = __floats2half2_rn(v2, v3);
            } else {
                *(float2*)&C[(size_t)r0 * ldc + c]       = make_float2(v0, v1);
                *(float2*)&C[(size_t)(r0 + 8) * ldc + c] = make_float2(v2, v3);
            }
        }
    }
}

// ---------------------------------------------------------------------------
// MHA core per (l, b): both heads per block. float4 global loads; fp32 smem
// rows padded to 132 floats (conflict-free); PV via float2 pairs.
// ---------------------------------------------------------------------------
#define AP2 132

__global__ __launch_bounds__(768)
void attn_kernel(const __half* __restrict__ qkv, const float* __restrict__ mask,
                 __half* __restrict__ att) {
    cudaGridDependencySynchronize();
    int bid = blockIdx.x;
    int b = bid & 63;
    int l = bid >> 6;

    __shared__ __align__(16) float qs[RR * AP2];
    __shared__ __align__(16) float ks[32 * AP2];   // rows 24..31 zeroed
    __shared__ __align__(16) float vs[RR * AP2];
    __shared__ float ps[RR * 32];

    int tid = threadIdx.x;
    // load 24 rows x 48 float4 (8 halves each), coalesced LDG.128
    for (int idx = tid; idx < RR * 48; idx += 768) {
        int s = idx / 48;
        int u = idx % 48;
        float4 raw = ((const float4*)(qkv + ((size_t)(l * RR + s) * BB + b) * 384))[u];
        const __half2* hp = (const __half2*)&raw;
        float2 f0 = __half22float2(hp[0]);
        float2 f1 = __half22float2(hp[1]);
        float2 f2 = __half22float2(hp[2]);
        float2 f3 = __half22float2(hp[3]);
        int seg = u >> 4;          // 0=q, 1=k, 2=v
        int w8 = (u & 15) * 8;
        float* dst = (seg == 0) ? &qs[s * AP2 + w8]
                   : (seg == 1) ? &ks[s * AP2 + w8]
                                : &vs[s * AP2 + w8];
        *(float4*)dst       = make_float4(f0.x, f0.y, f1.x, f1.y);
        *(float4*)(dst + 4) = make_float4(f2.x, f2.y, f3.x, f3.y);
    }
    for (int idx = tid; idx < 8 * 128; idx += 768) {   // zero ks pad rows
        int s = RR + (idx >> 7), d = idx & 127;
        ks[s * AP2 + d] = 0.f;
    }
    __syncthreads();

    int w = tid >> 5, lane = tid & 31;
    if (w >= RR) return;
    int r = w;
    float mk = (lane < RR) ? mask[r * RR + lane] : 0.f;

#pragma unroll
    for (int h = 0; h < 2; ++h) {
        int hb = h * 64;
        float4 a4 = make_float4(0.f, 0.f, 0.f, 0.f);
#pragma unroll
        for (int d4 = 0; d4 < 16; ++d4) {
            float4 qv = *(const float4*)&qs[r * AP2 + hb + 4 * d4];
            float4 kv = *(const float4*)&ks[lane * AP2 + hb + 4 * d4];
            a4.x = fmaf(qv.x, kv.x, a4.x);
            a4.y = fmaf(qv.y, kv.y, a4.y);
            a4.z = fmaf(qv.z, kv.z, a4.z);
            a4.w = fmaf(qv.w, kv.w, a4.w);
        }
        float sc = (a4.x + a4.y) + (a4.z + a4.w);
        float sco = (lane < RR) ? sc * 0.125f + mk : -INFINITY;

        float mx = sco;
#pragma unroll
        for (int off = 16; off; off >>= 1)
            mx = fmaxf(mx, __shfl_xor_sync(0xffffffffu, mx, off));
        float e = __expf(sco - mx);
        float sum = e;
#pragma unroll
        for (int off = 16; off; off >>= 1)
            sum += __shfl_xor_sync(0xffffffffu, sum, off);
        ps[r * 32 + lane] = e / sum;
        __syncwarp();

        // PV: lane handles dims (2*lane, 2*lane+1)
        float acc0 = 0.f, acc1 = 0.f;
#pragma unroll
        for (int s = 0; s < RR; ++s) {
            float p = ps[r * 32 + s];
            float2 v01 = *(const float2*)&vs[s * AP2 + hb + 2 * lane];
            acc0 = fmaf(p, v01.x, acc0);
            acc1 = fmaf(p, v01.y, acc1);
        }
        int mo = ((l * RR + r) * BB + b) * EMB + hb;
        *(__half2*)&att[mo + 2 * lane] = __floats2half2_rn(acc0, acc1);
        __syncwarp();
    }
}

// ---------------------------------------------------------------------------
// Gate / state update / outputs. g, g2 fp16 (g2 optional split-K partial).
// ---------------------------------------------------------------------------
__global__ __launch_bounds__(256)
void gate_kernel(const __half* __restrict__ g,
                 const __half* __restrict__ g2,
                 const __half* __restrict__ hin,
                 __half* __restrict__ hout,
                 const float* __restrict__ Bias,
                 float* __restrict__ out_all,
                 float* __restrict__ out_col,
                 float* __restrict__ out_row,
                 int s) {
    cudaGridDependencySynchronize();
    int idx = blockIdx.x * 256 + threadIdx.x;   // M1*HH/4 = 98304
    int c = idx & 63;
    int m = idx >> 6;
    int b = m & 63;
    int r = m >> 6;

    float4 q[6];
    {
        const __half2* Gh = (const __half2*)(g + (size_t)m * 1536);
#pragma unroll
        for (int t = 0; t < 6; ++t) {
            float2 a = __half22float2(Gh[t * 128 + 2 * c]);
            float2 bb = __half22float2(Gh[t * 128 + 2 * c + 1]);
            q[t] = make_float4(a.x, a.y, bb.x, bb.y);
        }
    }
    if (g2) {
        const __half2* Gh = (const __half2*)(g2 + (size_t)m * 1536);
#pragma unroll
        for (int t = 0; t < 6; ++t) {
            float2 a = __half22float2(Gh[t * 128 + 2 * c]);
            float2 bb = __half22float2(Gh[t * 128 + 2 * c + 1]);
            q[t].x += a.x; q[t].y += a.y; q[t].z += bb.x; q[t].w += bb.y;
        }
    }
    if (r <= s && s < RR) {
        const float4* B4 = (const float4*)Bias;
#pragma unroll
        for (int t = 0; t < 6; ++t) {
            float4 bb = B4[c + t * 64];
            q[t].x += bb.x; q[t].y += bb.y; q[t].z += bb.z; q[t].w += bb.w;
        }
    }
    float* qa = (float*)q;

    const __half2* HR = (const __half2*)(hin + (size_t)m * 512) + c * 2;
    const __half2* HC = (const __half2*)(hin + (size_t)m * 512 + 256) + c * 2;
    float2 hr01 = __half22float2(HR[0]);
    float2 hr23 = __half22float2(HR[1]);
    float2 hc01 = __half22float2(HC[0]);
    float2 hc23 = __half22float2(HC[1]);
    float hrp[4] = {hr01.x, hr01.y, hr23.x, hr23.y};
    float hcp[4] = {hc01.x, hc01.y, hc23.x, hc23.y};

    float hr[4], hc[4];
#pragma unroll
    for (int t = 0; t < 4; ++t) {
        float ug_r = sigf(qa[t]);
        float og_r = sigf(qa[4 + t]);
        float ug_c = sigf(qa[8 + t]);
        float og_c = sigf(qa[12 + t]);
        float ig_r = tanha(qa[16 + t]);
        float ig_c = tanha(qa[20 + t]);
        hr[t] = tanha((1.f - ug_r) * hrp[t] + ug_r * ig_r) * og_r;
        hc[t] = tanha((1.f - ug_c) * hcp[t] + ug_c * ig_c) * og_c;
    }
    float4 hr4 = make_float4(hr[0], hr[1], hr[2], hr[3]);
    float4 hc4 = make_float4(hc[0], hc[1], hc[2], hc[3]);

    int r2 = (r + 1) % RR;
    int mc = r2 * BB + b;
    __half2* OR = (__half2*)(hout + (size_t)m * 512) + c * 2;
    __half2* OC = (__half2*)(hout + (size_t)mc * 512 + 256) + c * 2;
    OR[0] = __floats2half2_rn(hr[0], hr[1]);
    OR[1] = __floats2half2_rn(hr[2], hr[3]);
    OC[0] = __floats2half2_rn(hc[0], hc[1]);
    OC[1] = __floats2half2_rn(hc[2], hc[3]);

    float* ob = out_all + ((size_t)m * LSTEPS + s) * 512;
    __stcs((float4*)ob + c, hr4);
    __stcs((float4*)(ob + 256) + c, hc4);

    if (s >= OO - 1) {
        int t2 = s - (OO - 1);
        if (r == t2)      ((float4*)(out_row + (size_t)(b * RR + t2) * HH))[c] = hr4;
        if (r == RR - 1)  ((float4*)(out_col + (size_t)(b * OO + t2) * HH))[c] = hc4;
    }
}

// ---------------------------------------------------------------------------
// Launch
// ---------------------------------------------------------------------------
extern "C" void kernel_launch(void* const* d_in, const int* in_sizes, int n_in,
                              void* d_out, int out_size) {
    const float* input = (const float*)d_in[0];
    const float* mask  = (const float*)d_in[1];
    const float* W     = (const float*)d_in[2];
    const float* Bias  = (const float*)d_in[3];
    const float* inw   = (const float*)d_in[4];
    const float* inb   = (const float*)d_in[5];
    const float* outw  = (const float*)d_in[6];
    const float* outb  = (const float*)d_in[7];
    float* out = (float*)d_out;

    __half *xy, *qkv, *att, *pre, *ht, *g, *Wt, *inwt, *outwt;
    cudaGetSymbolAddress((void**)&xy,    d_xy);
    cudaGetSymbolAddress((void**)&qkv,   d_qkv);
    cudaGetSymbolAddress((void**)&att,   d_att);
    cudaGetSymbolAddress((void**)&pre,   d_pre);
    cudaGetSymbolAddress((void**)&ht,    d_ht);
    cudaGetSymbolAddress((void**)&g,     d_g);
    cudaGetSymbolAddress((void**)&Wt,    d_Wt);
    cudaGetSymbolAddress((void**)&inwt,  d_inwt);
    cudaGetSymbolAddress((void**)&outwt, d_outwt);

    cudaFuncSetAttribute(gemm_mma, cudaFuncAttributeMaxDynamicSharedMemorySize, 65536);
    const int SMEMB = 65536;

    // 0) one-time weight conversion to fp16
    cvt_all_kernel<<<(W4 + IW4 + OW4 + 255) / 256, 256>>>(W, Wt, inw, inwt, outw, outwt);

    // 1) x (fp16)
    build_x_kernel<<<(MALL * 32 + 255) / 256, 256>>>(input, xy);

    // 2) qkv = x @ in_proj_wᵀ + b  (fp16 out)
    gemm_mma<<<dim3(3, MALL / 128), 256, SMEMB>>>(xy, 256, inwt, EMB, inb,
                                                  nullptr, 0,
                                                  (float*)qkv, 384, EMB, 1, 0);

    // 3) attention (fp16 in/out, both heads per block)
    attn_kernel<<<LSTEPS * BB, 768>>>(qkv, mask, att);

    // 4) y = att @ out_proj_wᵀ + b -> xy[:,128:256] (fp16 out)
    gemm_mma<<<dim3(1, MALL / 128), 256, SMEMB>>>(att, EMB, outwt, EMB, outb,
                                                  nullptr, 0,
                                                  (float*)(xy + 128), 256, EMB, 1, 0);

    // 5) pre = [x|y] @ W[:, 512:768]ᵀ (fp16 out)
    gemm_mma<<<dim3(12, MALL / 128), 256, SMEMB>>>(xy, 256, Wt + 512, 768, nullptr,
                                                   nullptr, 0,
                                                   (float*)pre, 1536, 256, 1, 0);

    // 6) zero initial state (buffer 0)
    cudaMemsetAsync(ht, 0, (size_t)M1 * 512 * sizeof(__half));

    // PDL launch configs for the scan loop
    cudaLaunchAttribute pdlAttr[1];
    pdlAttr[0].id = cudaLaunchAttributeProgrammaticStreamSerialization;
    pdlAttr[0].val.programmaticStreamSerializationAllowed = 1;

    cudaLaunchConfig_t cfgGemm = {};
    cfgGemm.gridDim  = dim3(12, 12, 2);      // split-K = 2
    cfgGemm.blockDim = dim3(256);
    cfgGemm.dynamicSmemBytes = SMEMB;
    cfgGemm.stream = 0;
    cfgGemm.attrs = pdlAttr;
    cfgGemm.numAttrs = 1;

    cudaLaunchConfig_t cfgGate = {};
    cfgGate.gridDim  = dim3(384);
    cfgGate.blockDim = dim3(256);
    cfgGate.dynamicSmemBytes = 0;
    cfgGate.stream = 0;
    cfgGate.attrs = pdlAttr;
    cfgGate.numAttrs = 1;

    float* out_col = out + OUT_ALL_ELEMS;
    float* out_row = out + OUT_ALL_ELEMS + HID_ELEMS;
    __half* g1 = g + (size_t)M1 * 1536;

    // 7) sequential scan; s=0 skips the GEMM (h == 0 -> g == pre[0], fp16)
    gate_kernel<<<384, 256>>>(pre, (const __half*)nullptr, ht,
                              ht + (size_t)M1 * 512, Bias,
                              out, out_col, out_row, 0);
    for (int s = 1; s < LSTEPS; ++s) {
        const __half* hin = ht + (size_t)(s & 1) * M1 * 512;
        __half* hout      = ht + (size_t)((s + 1) & 1) * M1 * 512;
        cudaLaunchKernelEx(&cfgGemm, gemm_mma,
                           hin, 512, (const __half*)Wt, 768,
                           (const float*)nullptr,
                           (const void*)(pre + (size_t)s * M1 * 1536), 1,
                           (float*)g, 1536, 256, 1, 256);
        cudaLaunchKernelEx(&cfgGate, gate_kernel,
                           (const __half*)g, (const __half*)g1, hin, hout,
                           Bias, out, out_col, out_row, s);
    }
}